// round 11
// baseline (speedup 1.0000x reference)
#include <cuda_runtime.h>
#include <cuda_fp16.h>
#include <cstdint>

// ---------------- problem constants ----------------
#define NB 4
#define NS 4096
#define NDIN 2048
#define NDOUT 2048
#define NR 16
#define NE 12
#define NM (NB * NS)  // 16384

// ---------------- GEMM tiling ----------------
#define BM 256
#define BN 128
#define CK 32                    // K per chunk (fp16): 64B rows
#define NCHUNK (NDIN / CK)       // 64
#define NCHTOT (NCHUNK + 1)      // +1 LoRA chunk (K=16 zero-padded to 32)
#define NSTAGE 4

#define A_SZ (BM * 64)                       // 16384
#define B_SZ (BN * 64)                       // 8192
#define OF_B A_SZ
#define STAGE_SZ (A_SZ + B_SZ)               // 24576
#define SMEM_TOTAL (NSTAGE * STAGE_SZ)       // 98304 (1 CTA/SM)

// ---------------- scratch (device globals: allocation-free rule) ----------------
__device__ __align__(16) __half g_x16[(size_t)NM * NDIN];
__device__ __align__(16) __half g_w16[(size_t)NDOUT * NDIN];
__device__ __align__(16) __half g_lx16[(size_t)NM * 32];          // cols 16-31 = 0
__device__ __align__(16) __half g_cb16[(size_t)NB * NDOUT * 32];  // cols 16-31 = 0

// ---------------- PTX helpers (plain sm_80+ instructions only) ----------------
__device__ __forceinline__ uint32_t smem_u32(const void* p) {
    uint32_t a;
    asm("{ .reg .u64 t; cvta.to.shared.u64 t, %1; cvt.u32.u64 %0, t; }" : "=r"(a) : "l"(p));
    return a;
}
__device__ __forceinline__ void cp16(uint32_t saddr, const void* gptr) {
    asm volatile("cp.async.cg.shared.global [%0], [%1], 16;"
                 :: "r"(saddr), "l"(__cvta_generic_to_global(gptr)) : "memory");
}
__device__ __forceinline__ void cp_commit() {
    asm volatile("cp.async.commit_group;" ::: "memory");
}
__device__ __forceinline__ void cp_wait2() {
    asm volatile("cp.async.wait_group 2;" ::: "memory");
}
__device__ __forceinline__ void cp_wait1() {
    asm volatile("cp.async.wait_group 1;" ::: "memory");
}
#define LDSM4(r0, r1, r2, r3, addr)                                              \
    asm volatile("ldmatrix.sync.aligned.m8n8.x4.shared.b16 {%0,%1,%2,%3}, [%4];" \
                 : "=r"(r0), "=r"(r1), "=r"(r2), "=r"(r3) : "r"(addr))
#define MMAF16(c, a, b0, b1)                                                  \
    asm volatile("mma.sync.aligned.m16n8k16.row.col.f32.f16.f16.f32 "         \
                 "{%0,%1,%2,%3},{%4,%5,%6,%7},{%8,%9},{%0,%1,%2,%3};"         \
                 : "+f"((c)[0]), "+f"((c)[1]), "+f"((c)[2]), "+f"((c)[3])     \
                 : "r"((a)[0]), "r"((a)[1]), "r"((a)[2]), "r"((a)[3]),        \
                   "r"(b0), "r"(b1))

// 64B-row swizzle (validated R7/R9/R10): 16B-chunk' = ch ^ ((row>>1)&3)
__device__ __forceinline__ uint32_t swof(int row, int ch) {
    return (uint32_t)(row * 64 + ((ch ^ ((row >> 1) & 3)) << 4));
}

// ---------------- pre-kernels: fp32 -> fp16 RN conversion ----------------
union H8 { __half2 h[4]; uint4 u; };

__device__ __forceinline__ void cvt8h(const float* src, __half* dst, size_t i) {
    float4 v0 = *(const float4*)(src + i);
    float4 v1 = *(const float4*)(src + i + 4);
    H8 o;
    o.h[0] = __float22half2_rn(make_float2(v0.x, v0.y));
    o.h[1] = __float22half2_rn(make_float2(v0.z, v0.w));
    o.h[2] = __float22half2_rn(make_float2(v1.x, v1.y));
    o.h[3] = __float22half2_rn(make_float2(v1.z, v1.w));
    *(uint4*)(dst + i) = o.u;
}
__global__ void k_cvt_x(const float* __restrict__ x) {
    size_t i = ((size_t)blockIdx.x * 256 + threadIdx.x) * 8;
    cvt8h(x, g_x16, i);
}
__global__ void k_cvt_w_comb(const float* __restrict__ W_org,
                             const float* __restrict__ gate,
                             const float* __restrict__ W_up) {
    if (blockIdx.x < 2048) {
        size_t i = ((size_t)blockIdx.x * 256 + threadIdx.x) * 8;
        cvt8h(W_org, g_w16, i);
    } else {
        int idx = (blockIdx.x - 2048) * 256 + threadIdx.x;
        if (idx >= NB * NDOUT * NR) return;
        int b = idx / (NDOUT * NR);
        int orr = idx - b * (NDOUT * NR);
        int o = orr >> 4, r = orr & 15;
        float s = 0.f;
#pragma unroll
        for (int e = 0; e < NE; e++)
            s += __ldg(&gate[b * NE + e]) * __ldg(&W_up[(size_t)e * NDOUT * NR + orr]);
        size_t off = ((size_t)b * NDOUT + o) * 32;
        g_cb16[off + r] = __float2half_rn(s);
        g_cb16[off + 16 + r] = __float2half_rn(0.f);
    }
}

// ---------------- k_lx: lx[m,0:16] = x @ W_down^T via fp16 mma ----------------
#define LXW 65536                        // 16 n-rows x 2048 k x 2B (fp16 W_down)
#define LX_STG 16384                     // 128 rows x 64 k x 2B (128B rows)
#define LX_SMEM (LXW + 3 * LX_STG)       // 114688
#define LXCK 64
#define LXNCH (NDIN / LXCK)              // 32

__device__ __forceinline__ uint32_t lx_swof(int row, int ch) {   // 128B rows
    return (uint32_t)(row * 128 + ((ch ^ (row & 7)) << 4));
}
__device__ __forceinline__ void lx_issue(uint32_t sb, int s, int c, int rowBase, int tid) {
    uint32_t xs = sb + LXW + s * LX_STG;
#pragma unroll
    for (int j = 0; j < 8; j++) {
        int g = tid + 128 * j;
        int row = g >> 3, ch = g & 7;
        cp16(xs + lx_swof(row, ch),
             g_x16 + (size_t)(rowBase + row) * NDIN + c * LXCK + ch * 8);
    }
}

__global__ void __launch_bounds__(128, 1) k_lx(const float* __restrict__ Wd) {
    extern __shared__ char sm[];
    const uint32_t sb = smem_u32(sm);
    const int tid = threadIdx.x;
    const int w = tid >> 5, lane = tid & 31;
    const int rowBase = blockIdx.x * 128;
    const int lr = lane & 15, lc = lane >> 4;

    for (int idx = tid; idx < 16 * 256; idx += 128) {
        int n = idx >> 8, ch = idx & 255;
        const float* s8 = Wd + (size_t)n * NDIN + ch * 8;
        float4 v0 = *(const float4*)s8;
        float4 v1 = *(const float4*)(s8 + 4);
        H8 o;
        o.h[0] = __float22half2_rn(make_float2(v0.x, v0.y));
        o.h[1] = __float22half2_rn(make_float2(v0.z, v0.w));
        o.h[2] = __float22half2_rn(make_float2(v1.x, v1.y));
        o.h[3] = __float22half2_rn(make_float2(v1.z, v1.w));
        *(uint4*)(sm + n * 4096 + ((ch ^ (n & 7)) << 4)) = o.u;
    }

    float acc[2][2][4];
#pragma unroll
    for (int i = 0; i < 2; i++)
#pragma unroll
        for (int j = 0; j < 2; j++)
#pragma unroll
            for (int q = 0; q < 4; q++) acc[i][j][q] = 0.f;

    lx_issue(sb, 0, 0, rowBase, tid); cp_commit();
    lx_issue(sb, 1, 1, rowBase, tid); cp_commit();

    for (int c = 0; c < LXNCH; c++) {
        cp_wait1();
        __syncthreads();
        if (c + 2 < LXNCH) lx_issue(sb, (c + 2) % 3, c + 2, rowBase, tid);
        cp_commit();
        const uint32_t xs = sb + LXW + (c % 3) * LX_STG;
#pragma unroll
        for (int ks = 0; ks < 4; ks++) {
            int K = c * 4 + ks;
            uint32_t chB = (uint32_t)(2 * K + lc);
            uint32_t r0, r1, r2, r3;
            LDSM4(r0, r1, r2, r3, sb + lr * 4096 + ((chB ^ (lr & 7)) << 4));
            uint32_t bf0[2] = {r0, r2}, bf1[2] = {r1, r3};
#pragma unroll
            for (int mt = 0; mt < 2; mt++) {
                int row = w * 32 + mt * 16 + lr;
                uint32_t ch = (uint32_t)(ks * 2 + lc);
                uint32_t a[4];
                LDSM4(a[0], a[1], a[2], a[3],
                      xs + row * 128 + ((ch ^ (row & 7)) << 4));
                MMAF16(acc[mt][0], a, bf0[0], bf0[1]);
                MMAF16(acc[mt][1], a, bf1[0], bf1[1]);
            }
        }
        __syncthreads();
    }

#pragma unroll
    for (int mt = 0; mt < 2; mt++) {
        int row = rowBase + w * 32 + mt * 16 + (lane >> 2);
#pragma unroll
        for (int nt = 0; nt < 2; nt++) {
            int col = nt * 8 + (lane & 3) * 2;
            *(__half2*)&g_lx16[(size_t)row * 32 + col] =
                __float22half2_rn(make_float2(acc[mt][nt][0], acc[mt][nt][1]));
            *(__half2*)&g_lx16[(size_t)(row + 8) * 32 + col] =
                __float22half2_rn(make_float2(acc[mt][nt][2], acc[mt][nt][3]));
        }
    }
    {
        int m = rowBase + tid;
        uint4 z = make_uint4(0, 0, 0, 0);
        *(uint4*)&g_lx16[(size_t)m * 32 + 16] = z;
        *(uint4*)&g_lx16[(size_t)m * 32 + 24] = z;
    }
}

// ---------------- main GEMM: fp16, 256x128 CTA, 8 warps of 64x64 ----------------
__global__ void __launch_bounds__(256, 1) k_gemm(float* __restrict__ out) {
    extern __shared__ char smem[];
    const uint32_t sb0 = smem_u32(smem);
    const int tid = threadIdx.x;
    const int wid = tid >> 5, lane = tid & 31;
    const int wm = wid >> 1, wn = wid & 1;      // 4x2 warp grid, warp tile 64x64
    const int rowBase = blockIdx.y * BM;
    const int colBase = blockIdx.x * BN;
    const int b = blockIdx.y >> 4;              // NS/BM = 16 row-blocks per batch
    const int lr = lane & 15, lc = lane >> 4;

    // fragment bases (swizzle folded; 16-row group advance = +1024B, ch via XOR)
    uint32_t aOff0, bOff0;
    {
        int ra = wm * 64 + lr;
        aOff0 = (uint32_t)(ra * 64 + (((ra >> 1) & 3) << 4));
        int rb = wn * 64 + lr;
        bOff0 = OF_B + (uint32_t)(rb * 64 + (((rb >> 1) & 3) << 4));
    }

    // loader: A 4 cp16/thread (256 rows), B 2 cp16/thread (128 rows)
    const int lrow = tid >> 2, lch = tid & 3;           // lrow 0..63
    const uint32_t soA = swof(lrow, lch);               // + j*4096 (64 rows)
    const uint32_t soB = swof(lrow, lch);               // + j*4096
    const __half* aG = g_x16 + (size_t)(rowBase + lrow) * NDIN + lch * 8;
    const __half* bG = g_w16 + (size_t)(colBase + lrow) * NDIN + lch * 8;
    const __half* aL = g_lx16 + (size_t)(rowBase + lrow) * 32 + lch * 8;
    const __half* bL = g_cb16 + ((size_t)b * NDOUT + colBase + lrow) * 32 + lch * 8;

    float acc[4][8][4];
#pragma unroll
    for (int i = 0; i < 4; i++)
#pragma unroll
        for (int j = 0; j < 8; j++)
#pragma unroll
            for (int q = 0; q < 4; q++) acc[i][j][q] = 0.f;

#pragma unroll
    for (int p = 0; p < 3; p++) {   // prologue: chunks 0,1,2
        uint32_t s = sb0 + p * STAGE_SZ;
#pragma unroll
        for (int j = 0; j < 4; j++)
            cp16(s + soA + j * 4096, aG + p * CK + (size_t)j * 64 * NDIN);
#pragma unroll
        for (int j = 0; j < 2; j++)
            cp16(s + OF_B + soB + j * 4096, bG + p * CK + (size_t)j * 64 * NDIN);
        cp_commit();
    }

    for (int kc = 0; kc < NCHTOT; kc++) {
        cp_wait2();
        __syncthreads();   // chunk kc ready; all warps done with slot (kc-1)&3

        const int nk = kc + 3;
        if (nk < NCHTOT) {
            uint32_t s = sb0 + (nk & 3) * STAGE_SZ;
            if (nk < NCHUNK) {
#pragma unroll
                for (int j = 0; j < 4; j++)
                    cp16(s + soA + j * 4096, aG + nk * CK + (size_t)j * 64 * NDIN);
#pragma unroll
                for (int j = 0; j < 2; j++)
                    cp16(s + OF_B + soB + j * 4096, bG + nk * CK + (size_t)j * 64 * NDIN);
            } else {  // LoRA chunk: rows of 32 fp16 = 64B
#pragma unroll
                for (int j = 0; j < 4; j++)
                    cp16(s + soA + j * 4096, aL + (size_t)j * 64 * 32);
#pragma unroll
                for (int j = 0; j < 2; j++)
                    cp16(s + OF_B + soB + j * 4096, bL + (size_t)j * 64 * 32);
            }
        }
        cp_commit();

        const uint32_t Sb = sb0 + (kc & 3) * STAGE_SZ;
#pragma unroll
        for (int ks = 0; ks < 2; ks++) {             // k16 per step
            const uint32_t cx = (uint32_t)((ks << 1) | lc) << 4;
            uint32_t bf[8][2];
#pragma unroll
            for (int bp = 0; bp < 4; bp++) {
                uint32_t r0, r1, r2, r3;
                LDSM4(r0, r1, r2, r3, Sb + ((bOff0 + bp * 1024) ^ cx));
                bf[bp * 2 + 0][0] = r0; bf[bp * 2 + 0][1] = r2;
                bf[bp * 2 + 1][0] = r1; bf[bp * 2 + 1][1] = r3;
            }
            uint32_t a[2][4];
            LDSM4(a[0][0], a[0][1], a[0][2], a[0][3], Sb + (aOff0 ^ cx));
#pragma unroll
            for (int mt = 0; mt < 4; mt++) {
                if (mt < 3) {
                    uint32_t* an = a[(mt + 1) & 1];
                    LDSM4(an[0], an[1], an[2], an[3],
                          Sb + ((aOff0 + (mt + 1) * 1024) ^ cx));
                }
                const uint32_t* ac = a[mt & 1];
#pragma unroll
                for (int nt = 0; nt < 8; nt++)
                    MMAF16(acc[mt][nt], ac, bf[nt][0], bf[nt][1]);
            }
        }
    }

    // ---------------- epilogue ----------------
#pragma unroll
    for (int mt = 0; mt < 4; mt++) {
#pragma unroll
        for (int nt = 0; nt < 8; nt++) {
            int row = rowBase + wm * 64 + mt * 16 + (lane >> 2);
            int col = colBase + wn * 64 + nt * 8 + (lane & 3) * 2;
            *(float2*)&out[(size_t)row * NDOUT + col] =
                make_float2(acc[mt][nt][0], acc[mt][nt][1]);
            *(float2*)&out[(size_t)(row + 8) * NDOUT + col] =
                make_float2(acc[mt][nt][2], acc[mt][nt][3]);
        }
    }
}

// ---------------- launch ----------------
extern "C" void kernel_launch(void* const* d_in, const int* in_sizes, int n_in,
                              void* d_out, int out_size) {
    const float* x      = (const float*)d_in[0];
    const float* gate   = (const float*)d_in[1];
    const float* W_org  = (const float*)d_in[2];
    const float* W_down = (const float*)d_in[3];
    const float* W_up   = (const float*)d_in[4];
    float* out = (float*)d_out;

    cudaFuncSetAttribute(k_gemm, cudaFuncAttributeMaxDynamicSharedMemorySize, SMEM_TOTAL);
    cudaFuncSetAttribute(k_lx, cudaFuncAttributeMaxDynamicSharedMemorySize, LX_SMEM);

    k_cvt_x<<<(size_t)NM * NDIN / 2048, 256>>>(x);
    k_cvt_w_comb<<<2048 + 512, 256>>>(W_org, gate, W_up);
    k_lx<<<NM / 128, 128, LX_SMEM>>>(W_down);

    dim3 grid(NDOUT / BN, NM / BM);   // (16, 64) = 1024 CTAs
    k_gemm<<<grid, 256, SMEM_TOTAL>>>(out);
}

// round 12
// speedup vs baseline: 1.0562x; 1.0562x over previous
#include <cuda_runtime.h>
#include <cuda_fp16.h>
#include <cstdint>

// ---------------- problem constants ----------------
#define NB 4
#define NS 4096
#define NDIN 2048
#define NDOUT 2048
#define NR 16
#define NE 12
#define NM (NB * NS)  // 16384

// ---------------- GEMM tiling ----------------
#define BM 128
#define BN 128
#define CK 32                    // K per chunk (fp16): 64B rows
#define NCHUNK (NDIN / CK)       // 64
#define NCHTOT (NCHUNK + 1)      // +1 LoRA chunk (K=16 zero-padded to 32)
#define NSTAGE 5

#define PART_SZ 8192                         // 128 rows x 64B
#define OF_B PART_SZ
#define STAGE_SZ (2 * PART_SZ)               // 16384
#define SMEM_TOTAL (NSTAGE * STAGE_SZ)       // 81920 (x2 CTAs = 160KB/SM)

// ---------------- scratch (device globals: allocation-free rule) ----------------
__device__ __align__(16) __half g_x16[(size_t)NM * NDIN];
__device__ __align__(16) __half g_w16[(size_t)NDOUT * NDIN];
__device__ __align__(16) __half g_lx16[(size_t)NM * 32];          // cols 16-31 = 0
__device__ __align__(16) __half g_cb16[(size_t)NB * NDOUT * 32];  // cols 16-31 = 0

// ---------------- PTX helpers (plain sm_80+ instructions only) ----------------
__device__ __forceinline__ uint32_t smem_u32(const void* p) {
    uint32_t a;
    asm("{ .reg .u64 t; cvta.to.shared.u64 t, %1; cvt.u32.u64 %0, t; }" : "=r"(a) : "l"(p));
    return a;
}
__device__ __forceinline__ void cp16(uint32_t saddr, const void* gptr) {
    asm volatile("cp.async.cg.shared.global [%0], [%1], 16;"
                 :: "r"(saddr), "l"(__cvta_generic_to_global(gptr)) : "memory");
}
__device__ __forceinline__ void cp_commit() {
    asm volatile("cp.async.commit_group;" ::: "memory");
}
__device__ __forceinline__ void cp_wait3() {
    asm volatile("cp.async.wait_group 3;" ::: "memory");
}
__device__ __forceinline__ void cp_wait1() {
    asm volatile("cp.async.wait_group 1;" ::: "memory");
}
#define LDSM4(r0, r1, r2, r3, addr)                                              \
    asm volatile("ldmatrix.sync.aligned.m8n8.x4.shared.b16 {%0,%1,%2,%3}, [%4];" \
                 : "=r"(r0), "=r"(r1), "=r"(r2), "=r"(r3) : "r"(addr))
#define MMAF16(c, a, b0, b1)                                                  \
    asm volatile("mma.sync.aligned.m16n8k16.row.col.f32.f16.f16.f32 "         \
                 "{%0,%1,%2,%3},{%4,%5,%6,%7},{%8,%9},{%0,%1,%2,%3};"         \
                 : "+f"((c)[0]), "+f"((c)[1]), "+f"((c)[2]), "+f"((c)[3])     \
                 : "r"((a)[0]), "r"((a)[1]), "r"((a)[2]), "r"((a)[3]),        \
                   "r"(b0), "r"(b1))

// 64B-row swizzle (validated R7-R11): 16B-chunk' = ch ^ ((row>>1)&3)
__device__ __forceinline__ uint32_t swof(int row, int ch) {
    return (uint32_t)(row * 64 + ((ch ^ ((row >> 1) & 3)) << 4));
}

// ---------------- pre-kernels: fp32 -> fp16 RN conversion ----------------
union H8 { __half2 h[4]; uint4 u; };

__device__ __forceinline__ void cvt8h(const float* src, __half* dst, size_t i) {
    float4 v0 = *(const float4*)(src + i);
    float4 v1 = *(const float4*)(src + i + 4);
    H8 o;
    o.h[0] = __float22half2_rn(make_float2(v0.x, v0.y));
    o.h[1] = __float22half2_rn(make_float2(v0.z, v0.w));
    o.h[2] = __float22half2_rn(make_float2(v1.x, v1.y));
    o.h[3] = __float22half2_rn(make_float2(v1.z, v1.w));
    *(uint4*)(dst + i) = o.u;
}
__global__ void k_cvt_x(const float* __restrict__ x) {
    size_t i = ((size_t)blockIdx.x * 256 + threadIdx.x) * 8;
    cvt8h(x, g_x16, i);
}
__global__ void k_cvt_w_comb(const float* __restrict__ W_org,
                             const float* __restrict__ gate,
                             const float* __restrict__ W_up) {
    if (blockIdx.x < 2048) {
        size_t i = ((size_t)blockIdx.x * 256 + threadIdx.x) * 8;
        cvt8h(W_org, g_w16, i);
    } else {
        int idx = (blockIdx.x - 2048) * 256 + threadIdx.x;
        if (idx >= NB * NDOUT * NR) return;
        int b = idx / (NDOUT * NR);
        int orr = idx - b * (NDOUT * NR);
        int o = orr >> 4, r = orr & 15;
        float s = 0.f;
#pragma unroll
        for (int e = 0; e < NE; e++)
            s += __ldg(&gate[b * NE + e]) * __ldg(&W_up[(size_t)e * NDOUT * NR + orr]);
        size_t off = ((size_t)b * NDOUT + o) * 32;
        g_cb16[off + r] = __float2half_rn(s);
        g_cb16[off + 16 + r] = __float2half_rn(0.f);
    }
}

// ---------------- k_lx: lx[m,0:16] = x @ W_down^T via fp16 mma ----------------
#define LXW 65536                        // 16 n-rows x 2048 k x 2B (fp16 W_down)
#define LX_STG 16384                     // 128 rows x 64 k x 2B (128B rows)
#define LX_SMEM (LXW + 3 * LX_STG)       // 114688
#define LXCK 64
#define LXNCH (NDIN / LXCK)              // 32

__device__ __forceinline__ uint32_t lx_swof(int row, int ch) {   // 128B rows
    return (uint32_t)(row * 128 + ((ch ^ (row & 7)) << 4));
}
__device__ __forceinline__ void lx_issue(uint32_t sb, int s, int c, int rowBase, int tid) {
    uint32_t xs = sb + LXW + s * LX_STG;
#pragma unroll
    for (int j = 0; j < 8; j++) {
        int g = tid + 128 * j;
        int row = g >> 3, ch = g & 7;
        cp16(xs + lx_swof(row, ch),
             g_x16 + (size_t)(rowBase + row) * NDIN + c * LXCK + ch * 8);
    }
}

__global__ void __launch_bounds__(128, 1) k_lx(const float* __restrict__ Wd) {
    extern __shared__ char sm[];
    const uint32_t sb = smem_u32(sm);
    const int tid = threadIdx.x;
    const int w = tid >> 5, lane = tid & 31;
    const int rowBase = blockIdx.x * 128;
    const int lr = lane & 15, lc = lane >> 4;

    for (int idx = tid; idx < 16 * 256; idx += 128) {
        int n = idx >> 8, ch = idx & 255;
        const float* s8 = Wd + (size_t)n * NDIN + ch * 8;
        float4 v0 = *(const float4*)s8;
        float4 v1 = *(const float4*)(s8 + 4);
        H8 o;
        o.h[0] = __float22half2_rn(make_float2(v0.x, v0.y));
        o.h[1] = __float22half2_rn(make_float2(v0.z, v0.w));
        o.h[2] = __float22half2_rn(make_float2(v1.x, v1.y));
        o.h[3] = __float22half2_rn(make_float2(v1.z, v1.w));
        *(uint4*)(sm + n * 4096 + ((ch ^ (n & 7)) << 4)) = o.u;
    }

    float acc[2][2][4];
#pragma unroll
    for (int i = 0; i < 2; i++)
#pragma unroll
        for (int j = 0; j < 2; j++)
#pragma unroll
            for (int q = 0; q < 4; q++) acc[i][j][q] = 0.f;

    lx_issue(sb, 0, 0, rowBase, tid); cp_commit();
    lx_issue(sb, 1, 1, rowBase, tid); cp_commit();

    for (int c = 0; c < LXNCH; c++) {
        cp_wait1();
        __syncthreads();
        if (c + 2 < LXNCH) lx_issue(sb, (c + 2) % 3, c + 2, rowBase, tid);
        cp_commit();
        const uint32_t xs = sb + LXW + (c % 3) * LX_STG;
#pragma unroll
        for (int ks = 0; ks < 4; ks++) {
            int K = c * 4 + ks;
            uint32_t chB = (uint32_t)(2 * K + lc);
            uint32_t r0, r1, r2, r3;
            LDSM4(r0, r1, r2, r3, sb + lr * 4096 + ((chB ^ (lr & 7)) << 4));
            uint32_t bf0[2] = {r0, r2}, bf1[2] = {r1, r3};
#pragma unroll
            for (int mt = 0; mt < 2; mt++) {
                int row = w * 32 + mt * 16 + lr;
                uint32_t ch = (uint32_t)(ks * 2 + lc);
                uint32_t a[4];
                LDSM4(a[0], a[1], a[2], a[3],
                      xs + row * 128 + ((ch ^ (row & 7)) << 4));
                MMAF16(acc[mt][0], a, bf0[0], bf0[1]);
                MMAF16(acc[mt][1], a, bf1[0], bf1[1]);
            }
        }
        __syncthreads();
    }

#pragma unroll
    for (int mt = 0; mt < 2; mt++) {
        int row = rowBase + w * 32 + mt * 16 + (lane >> 2);
#pragma unroll
        for (int nt = 0; nt < 2; nt++) {
            int col = nt * 8 + (lane & 3) * 2;
            *(__half2*)&g_lx16[(size_t)row * 32 + col] =
                __float22half2_rn(make_float2(acc[mt][nt][0], acc[mt][nt][1]));
            *(__half2*)&g_lx16[(size_t)(row + 8) * 32 + col] =
                __float22half2_rn(make_float2(acc[mt][nt][2], acc[mt][nt][3]));
        }
    }
    {
        int m = rowBase + tid;
        uint4 z = make_uint4(0, 0, 0, 0);
        *(uint4*)&g_lx16[(size_t)m * 32 + 16] = z;
        *(uint4*)&g_lx16[(size_t)m * 32 + 24] = z;
    }
}

// ---------------- main GEMM: fp16, 128x128 CTA, 16 warps of 64x32 ----------------
__global__ void __launch_bounds__(256, 2) k_gemm(float* __restrict__ out) {
    extern __shared__ char smem[];
    const uint32_t sb0 = smem_u32(smem);
    const int tid = threadIdx.x;
    const int wid = tid >> 5, lane = tid & 31;
    const int wm = wid >> 2, wn = wid & 3;      // 2x4 warp grid? -> 64x32 tiles 4x4 work split
    const int rowBase = blockIdx.y * BM;
    const int colBase = blockIdx.x * BN;
    const int b = blockIdx.y >> 5;              // NS/BM = 32 row-blocks per batch
    const int lr = lane & 15, lc = lane >> 4;

    // warp tile 64x32: wm in 0..1 selects 64-row band, wn in 0..3 selects 32-col band
    // fragment bases (swizzle folded; 16-row group advance = +1024B, ch via XOR)
    uint32_t aOff0, bOff0;
    {
        int ra = wm * 64 + lr;
        aOff0 = (uint32_t)(ra * 64 + (((ra >> 1) & 3) << 4));
        int rb = wn * 32 + lr;
        bOff0 = OF_B + (uint32_t)(rb * 64 + (((rb >> 1) & 3) << 4));
    }

    // loader: 2 A + 2 B cp16 per thread (128 rows x 4 chunks each)
    const int lrow = tid >> 2, lch = tid & 3;          // lrow 0..63
    const uint32_t so0 = swof(lrow, lch);              // + j*4096 (64 rows)
    const __half* aG = g_x16 + (size_t)(rowBase + lrow) * NDIN + lch * 8;
    const __half* bG = g_w16 + (size_t)(colBase + lrow) * NDIN + lch * 8;
    const __half* aL = g_lx16 + (size_t)(rowBase + lrow) * 32 + lch * 8;
    const __half* bL = g_cb16 + ((size_t)b * NDOUT + colBase + lrow) * 32 + lch * 8;

    float acc[4][4][4];
#pragma unroll
    for (int i = 0; i < 4; i++)
#pragma unroll
        for (int j = 0; j < 4; j++)
#pragma unroll
            for (int q = 0; q < 4; q++) acc[i][j][q] = 0.f;

#pragma unroll
    for (int p = 0; p < 4; p++) {   // prologue: chunks 0..3
        uint32_t s = sb0 + p * STAGE_SZ;
#pragma unroll
        for (int j = 0; j < 2; j++) {
            cp16(s + so0 + j * 4096, aG + p * CK + (size_t)j * 64 * NDIN);
            cp16(s + OF_B + so0 + j * 4096, bG + p * CK + (size_t)j * 64 * NDIN);
        }
        cp_commit();
    }

    int slot = 0;        // slot of chunk kc (mod 5)
    int nslot = 4;       // slot for chunk kc+4
    for (int kc = 0; kc < NCHTOT; kc++) {
        cp_wait3();
        __syncthreads();   // chunk kc ready; slot (kc-1)%5 free for reuse

        const int nk = kc + 4;
        if (nk < NCHTOT) {
            uint32_t s = sb0 + nslot * STAGE_SZ;
            if (nk < NCHUNK) {
#pragma unroll
                for (int j = 0; j < 2; j++) {
                    cp16(s + so0 + j * 4096, aG + nk * CK + (size_t)j * 64 * NDIN);
                    cp16(s + OF_B + so0 + j * 4096, bG + nk * CK + (size_t)j * 64 * NDIN);
                }
            } else {  // LoRA chunk: rows of 32 fp16 = 64B
#pragma unroll
                for (int j = 0; j < 2; j++) {
                    cp16(s + so0 + j * 4096, aL + (size_t)j * 64 * 32);
                    cp16(s + OF_B + so0 + j * 4096, bL + (size_t)j * 64 * 32);
                }
            }
        }
        cp_commit();

        const uint32_t Sb = sb0 + slot * STAGE_SZ;
        slot = (slot + 1 == NSTAGE) ? 0 : slot + 1;
        nslot = (nslot + 1 == NSTAGE) ? 0 : nslot + 1;
#pragma unroll
        for (int ks = 0; ks < 2; ks++) {             // k16 per step
            const uint32_t cx = (uint32_t)((ks << 1) | lc) << 4;
            // B fragments: 4 n-tiles via 2 LDSM.x4 (16 n-rows x k16 each)
            uint32_t bf[4][2];
#pragma unroll
            for (int bp = 0; bp < 2; bp++) {
                uint32_t r0, r1, r2, r3;
                LDSM4(r0, r1, r2, r3, Sb + ((bOff0 + bp * 1024) ^ cx));
                bf[bp * 2 + 0][0] = r0; bf[bp * 2 + 0][1] = r2;
                bf[bp * 2 + 1][0] = r1; bf[bp * 2 + 1][1] = r3;
            }
            uint32_t a[2][4];
            LDSM4(a[0][0], a[0][1], a[0][2], a[0][3], Sb + (aOff0 ^ cx));
#pragma unroll
            for (int mt = 0; mt < 4; mt++) {
                if (mt < 3) {
                    uint32_t* an = a[(mt + 1) & 1];
                    LDSM4(an[0], an[1], an[2], an[3],
                          Sb + ((aOff0 + (mt + 1) * 1024) ^ cx));
                }
                const uint32_t* ac = a[mt & 1];
#pragma unroll
                for (int nt = 0; nt < 4; nt++)
                    MMAF16(acc[mt][nt], ac, bf[nt][0], bf[nt][1]);
            }
        }
    }

    // ---------------- epilogue ----------------
#pragma unroll
    for (int mt = 0; mt < 4; mt++) {
#pragma unroll
        for (int nt = 0; nt < 4; nt++) {
            int row = rowBase + wm * 64 + mt * 16 + (lane >> 2);
            int col = colBase + wn * 32 + nt * 8 + (lane & 3) * 2;
            *(float2*)&out[(size_t)row * NDOUT + col] =
                make_float2(acc[mt][nt][0], acc[mt][nt][1]);
            *(float2*)&out[(size_t)(row + 8) * NDOUT + col] =
                make_float2(acc[mt][nt][2], acc[mt][nt][3]);
        }
    }
}

// ---------------- launch ----------------
extern "C" void kernel_launch(void* const* d_in, const int* in_sizes, int n_in,
                              void* d_out, int out_size) {
    const float* x      = (const float*)d_in[0];
    const float* gate   = (const float*)d_in[1];
    const float* W_org  = (const float*)d_in[2];
    const float* W_down = (const float*)d_in[3];
    const float* W_up   = (const float*)d_in[4];
    float* out = (float*)d_out;

    cudaFuncSetAttribute(k_gemm, cudaFuncAttributeMaxDynamicSharedMemorySize, SMEM_TOTAL);
    cudaFuncSetAttribute(k_lx, cudaFuncAttributeMaxDynamicSharedMemorySize, LX_SMEM);

    k_cvt_x<<<(size_t)NM * NDIN / 2048, 256>>>(x);
    k_cvt_w_comb<<<2048 + 512, 256>>>(W_org, gate, W_up);
    k_lx<<<NM / 128, 128, LX_SMEM>>>(W_down);

    dim3 grid(NDOUT / BN, NM / BM);   // (16, 128) = 2048 CTAs
    k_gemm<<<grid, 256, SMEM_TOTAL>>>(out);
}

// round 13
// speedup vs baseline: 1.1577x; 1.0961x over previous
#include <cuda_runtime.h>
#include <cuda_fp16.h>
#include <cstdint>

// ---------------- problem constants ----------------
#define NB 4
#define NS 4096
#define NDIN 2048
#define NDOUT 2048
#define NR 16
#define NE 12
#define NM (NB * NS)  // 16384

// ---------------- GEMM tiling ----------------
#define BM 128
#define BN 128
#define CK 64                    // K per chunk (fp16): 128B rows
#define NCHUNK (NDIN / CK)       // 32
#define NCHTOT (NCHUNK + 1)      // +1 LoRA chunk (K=16 zero-padded to 64)
#define NSTAGE 3

#define PART_SZ 16384                        // 128 rows x 128B
#define OF_B PART_SZ
#define STAGE_SZ (2 * PART_SZ)               // 32768
#define SMEM_TOTAL (NSTAGE * STAGE_SZ)       // 98304 (x2 CTAs = 192KB/SM)

// ---------------- scratch (device globals: allocation-free rule) ----------------
__device__ __align__(16) __half g_x16[(size_t)NM * NDIN];
__device__ __align__(16) __half g_w16[(size_t)NDOUT * NDIN];
__device__ __align__(16) __half g_lx16[(size_t)NM * 64];          // cols 16-63 = 0
__device__ __align__(16) __half g_cb16[(size_t)NB * NDOUT * 64];  // cols 16-63 = 0

// ---------------- PTX helpers (plain sm_80+ instructions only) ----------------
__device__ __forceinline__ uint32_t smem_u32(const void* p) {
    uint32_t a;
    asm("{ .reg .u64 t; cvta.to.shared.u64 t, %1; cvt.u32.u64 %0, t; }" : "=r"(a) : "l"(p));
    return a;
}
__device__ __forceinline__ void cp16(uint32_t saddr, const void* gptr) {
    asm volatile("cp.async.cg.shared.global [%0], [%1], 16;"
                 :: "r"(saddr), "l"(__cvta_generic_to_global(gptr)) : "memory");
}
__device__ __forceinline__ void cp_commit() {
    asm volatile("cp.async.commit_group;" ::: "memory");
}
__device__ __forceinline__ void cp_wait1() {
    asm volatile("cp.async.wait_group 1;" ::: "memory");
}
#define LDSM4(r0, r1, r2, r3, addr)                                              \
    asm volatile("ldmatrix.sync.aligned.m8n8.x4.shared.b16 {%0,%1,%2,%3}, [%4];" \
                 : "=r"(r0), "=r"(r1), "=r"(r2), "=r"(r3) : "r"(addr))
#define MMAF16(c, a, b0, b1)                                                  \
    asm volatile("mma.sync.aligned.m16n8k16.row.col.f32.f16.f16.f32 "         \
                 "{%0,%1,%2,%3},{%4,%5,%6,%7},{%8,%9},{%0,%1,%2,%3};"         \
                 : "+f"((c)[0]), "+f"((c)[1]), "+f"((c)[2]), "+f"((c)[3])     \
                 : "r"((a)[0]), "r"((a)[1]), "r"((a)[2]), "r"((a)[3]),        \
                   "r"(b0), "r"(b1))

// 128B-row swizzle (validated in k_lx since R7): 16B-chunk' = ch ^ (row&7)
__device__ __forceinline__ uint32_t swof(int row, int ch) {
    return (uint32_t)(row * 128 + ((ch ^ (row & 7)) << 4));
}

// ---------------- pre-kernels: fp32 -> fp16 RN conversion ----------------
union H8 { __half2 h[4]; uint4 u; };

__device__ __forceinline__ void cvt8h(const float* src, __half* dst, size_t i) {
    float4 v0 = *(const float4*)(src + i);
    float4 v1 = *(const float4*)(src + i + 4);
    H8 o;
    o.h[0] = __float22half2_rn(make_float2(v0.x, v0.y));
    o.h[1] = __float22half2_rn(make_float2(v0.z, v0.w));
    o.h[2] = __float22half2_rn(make_float2(v1.x, v1.y));
    o.h[3] = __float22half2_rn(make_float2(v1.z, v1.w));
    *(uint4*)(dst + i) = o.u;
}
__global__ void k_cvt_x(const float* __restrict__ x) {
    size_t i = ((size_t)blockIdx.x * 256 + threadIdx.x) * 8;
    cvt8h(x, g_x16, i);
}
__global__ void k_cvt_w_comb(const float* __restrict__ W_org,
                             const float* __restrict__ gate,
                             const float* __restrict__ W_up) {
    if (blockIdx.x < 2048) {
        size_t i = ((size_t)blockIdx.x * 256 + threadIdx.x) * 8;
        cvt8h(W_org, g_w16, i);
    } else {
        int idx = (blockIdx.x - 2048) * 256 + threadIdx.x;
        if (idx >= NB * NDOUT * NR) return;
        int b = idx / (NDOUT * NR);
        int orr = idx - b * (NDOUT * NR);
        int o = orr >> 4, r = orr & 15;
        float s = 0.f;
#pragma unroll
        for (int e = 0; e < NE; e++)
            s += __ldg(&gate[b * NE + e]) * __ldg(&W_up[(size_t)e * NDOUT * NR + orr]);
        size_t off = ((size_t)b * NDOUT + o) * 64;
        g_cb16[off + r] = __float2half_rn(s);
        if (r < 6) {  // zero cols 16..63 (6 x 8 halves)
            uint4 z = make_uint4(0, 0, 0, 0);
            *(uint4*)&g_cb16[off + 16 + r * 8] = z;
        }
    }
}

// ---------------- k_lx: lx[m,0:16] = x @ W_down^T via fp16 mma ----------------
#define LXW 65536                        // 16 n-rows x 2048 k x 2B (fp16 W_down)
#define LX_STG 16384                     // 128 rows x 64 k x 2B (128B rows)
#define LX_SMEM (LXW + 3 * LX_STG)       // 114688
#define LXCK 64
#define LXNCH (NDIN / LXCK)              // 32

__device__ __forceinline__ void lx_issue(uint32_t sb, int s, int c, int rowBase, int tid) {
    uint32_t xs = sb + LXW + s * LX_STG;
#pragma unroll
    for (int j = 0; j < 8; j++) {
        int g = tid + 128 * j;
        int row = g >> 3, ch = g & 7;
        cp16(xs + swof(row, ch),
             g_x16 + (size_t)(rowBase + row) * NDIN + c * LXCK + ch * 8);
    }
}

__global__ void __launch_bounds__(128, 1) k_lx(const float* __restrict__ Wd) {
    extern __shared__ char sm[];
    const uint32_t sb = smem_u32(sm);
    const int tid = threadIdx.x;
    const int w = tid >> 5, lane = tid & 31;
    const int rowBase = blockIdx.x * 128;
    const int lr = lane & 15, lc = lane >> 4;

    for (int idx = tid; idx < 16 * 256; idx += 128) {
        int n = idx >> 8, ch = idx & 255;
        const float* s8 = Wd + (size_t)n * NDIN + ch * 8;
        float4 v0 = *(const float4*)s8;
        float4 v1 = *(const float4*)(s8 + 4);
        H8 o;
        o.h[0] = __float22half2_rn(make_float2(v0.x, v0.y));
        o.h[1] = __float22half2_rn(make_float2(v0.z, v0.w));
        o.h[2] = __float22half2_rn(make_float2(v1.x, v1.y));
        o.h[3] = __float22half2_rn(make_float2(v1.z, v1.w));
        *(uint4*)(sm + n * 4096 + ((ch ^ (n & 7)) << 4)) = o.u;
    }

    float acc[2][2][4];
#pragma unroll
    for (int i = 0; i < 2; i++)
#pragma unroll
        for (int j = 0; j < 2; j++)
#pragma unroll
            for (int q = 0; q < 4; q++) acc[i][j][q] = 0.f;

    lx_issue(sb, 0, 0, rowBase, tid); cp_commit();
    lx_issue(sb, 1, 1, rowBase, tid); cp_commit();

    for (int c = 0; c < LXNCH; c++) {
        cp_wait1();
        __syncthreads();
        if (c + 2 < LXNCH) lx_issue(sb, (c + 2) % 3, c + 2, rowBase, tid);
        cp_commit();
        const uint32_t xs = sb + LXW + (c % 3) * LX_STG;
#pragma unroll
        for (int ks = 0; ks < 4; ks++) {
            int K = c * 4 + ks;
            uint32_t chB = (uint32_t)(2 * K + lc);
            uint32_t r0, r1, r2, r3;
            LDSM4(r0, r1, r2, r3, sb + lr * 4096 + ((chB ^ (lr & 7)) << 4));
            uint32_t bf0[2] = {r0, r2}, bf1[2] = {r1, r3};
#pragma unroll
            for (int mt = 0; mt < 2; mt++) {
                int row = w * 32 + mt * 16 + lr;
                uint32_t ch = (uint32_t)(ks * 2 + lc);
                uint32_t a[4];
                LDSM4(a[0], a[1], a[2], a[3],
                      xs + row * 128 + ((ch ^ (row & 7)) << 4));
                MMAF16(acc[mt][0], a, bf0[0], bf0[1]);
                MMAF16(acc[mt][1], a, bf1[0], bf1[1]);
            }
        }
        __syncthreads();
    }

    // epilogue: store into 64-wide padded array, zero cols 16-63
#pragma unroll
    for (int mt = 0; mt < 2; mt++) {
        int row = rowBase + w * 32 + mt * 16 + (lane >> 2);
#pragma unroll
        for (int nt = 0; nt < 2; nt++) {
            int col = nt * 8 + (lane & 3) * 2;
            *(__half2*)&g_lx16[(size_t)row * 64 + col] =
                __float22half2_rn(make_float2(acc[mt][nt][0], acc[mt][nt][1]));
            *(__half2*)&g_lx16[(size_t)(row + 8) * 64 + col] =
                __float22half2_rn(make_float2(acc[mt][nt][2], acc[mt][nt][3]));
        }
    }
    {
        int m = rowBase + tid;
        uint4 z = make_uint4(0, 0, 0, 0);
#pragma unroll
        for (int zz = 0; zz < 6; zz++)
            *(uint4*)&g_lx16[(size_t)m * 64 + 16 + zz * 8] = z;
    }
}

// ---------------- main GEMM: fp16, 128x128 CTA, 16 warps of 64x32, CK=64 ----------------
__global__ void __launch_bounds__(256, 2) k_gemm(float* __restrict__ out) {
    extern __shared__ char smem[];
    const uint32_t sb0 = smem_u32(smem);
    const int tid = threadIdx.x;
    const int wid = tid >> 5, lane = tid & 31;
    const int wm = wid >> 2, wn = wid & 3;      // warp tile 64x32
    const int rowBase = blockIdx.y * BM;
    const int colBase = blockIdx.x * BN;
    const int b = blockIdx.y >> 5;              // NS/BM = 32 row-blocks per batch
    const int lr = lane & 15, lc = lane >> 4;
    const uint32_t sw7 = (uint32_t)(lr & 7);    // same swizzle key for ALL tiles

    // fragment bases: tile advance = +2048B; k-select via precomputed cx[ks]
    const uint32_t aBase0 = (uint32_t)((wm * 64 + lr) * 128);
    const uint32_t bBase0 = OF_B + (uint32_t)((wn * 32 + lr) * 128);
    uint32_t cx[4];
#pragma unroll
    for (int ks = 0; ks < 4; ks++)
        cx[ks] = ((uint32_t)(2 * ks + lc) ^ sw7) << 4;

    // loader: 4 A + 4 B cp16 per thread (128 rows x 8 chunks each)
    const int lrow = tid >> 3, lch = tid & 7;   // lrow 0..31
    const uint32_t so0 = swof(lrow, lch);       // + j*4096 (32 rows; row&7 invariant)
    const __half* aG = g_x16 + (size_t)(rowBase + lrow) * NDIN + lch * 8;
    const __half* bG = g_w16 + (size_t)(colBase + lrow) * NDIN + lch * 8;
    const __half* aL = g_lx16 + (size_t)(rowBase + lrow) * 64 + lch * 8;
    const __half* bL = g_cb16 + ((size_t)b * NDOUT + colBase + lrow) * 64 + lch * 8;

    float acc[4][4][4];
#pragma unroll
    for (int i = 0; i < 4; i++)
#pragma unroll
        for (int j = 0; j < 4; j++)
#pragma unroll
            for (int q = 0; q < 4; q++) acc[i][j][q] = 0.f;

#pragma unroll
    for (int p = 0; p < 2; p++) {   // prologue: chunks 0,1
        uint32_t s = sb0 + p * STAGE_SZ;
#pragma unroll
        for (int j = 0; j < 4; j++) {
            cp16(s + so0 + j * 4096, aG + p * CK + (size_t)j * 32 * NDIN);
            cp16(s + OF_B + so0 + j * 4096, bG + p * CK + (size_t)j * 32 * NDIN);
        }
        cp_commit();
    }

    int slot = 0, nslot = 2;
    for (int kc = 0; kc < NCHTOT; kc++) {
        cp_wait1();
        __syncthreads();   // chunk kc ready; slot (kc-1)%3 free

        const int nk = kc + 2;
        if (nk < NCHTOT) {
            uint32_t s = sb0 + nslot * STAGE_SZ;
            if (nk < NCHUNK) {
#pragma unroll
                for (int j = 0; j < 4; j++) {
                    cp16(s + so0 + j * 4096, aG + nk * CK + (size_t)j * 32 * NDIN);
                    cp16(s + OF_B + so0 + j * 4096, bG + nk * CK + (size_t)j * 32 * NDIN);
                }
            } else {  // LoRA chunk: rows of 64 fp16 = 128B
#pragma unroll
                for (int j = 0; j < 4; j++) {
                    cp16(s + so0 + j * 4096, aL + (size_t)j * 32 * 64);
                    cp16(s + OF_B + so0 + j * 4096, bL + (size_t)j * 32 * 64);
                }
            }
        }
        cp_commit();

        const uint32_t Sb = sb0 + slot * STAGE_SZ;
        slot = (slot + 1 == NSTAGE) ? 0 : slot + 1;
        nslot = (nslot + 1 == NSTAGE) ? 0 : nslot + 1;

        // ---- fragment-pipelined compute: 4 ks x 4 mt steps ----
        uint32_t bfb[2][4][2];     // B frags, double-buffered by ks parity
        uint32_t a[2][4];          // A frags, double-buffered by step parity
        {   // chunk prologue frags
            uint32_t r0, r1, r2, r3;
            LDSM4(r0, r1, r2, r3, Sb + bBase0 + cx[0]);
            bfb[0][0][0] = r0; bfb[0][0][1] = r2;
            bfb[0][1][0] = r1; bfb[0][1][1] = r3;
            LDSM4(r0, r1, r2, r3, Sb + bBase0 + 2048 + cx[0]);
            bfb[0][2][0] = r0; bfb[0][2][1] = r2;
            bfb[0][3][0] = r1; bfb[0][3][1] = r3;
            LDSM4(a[0][0], a[0][1], a[0][2], a[0][3], Sb + aBase0 + cx[0]);
        }
#pragma unroll
        for (int ks = 0; ks < 4; ks++) {
            const int cur = ks & 1;
#pragma unroll
            for (int mt = 0; mt < 4; mt++) {
                if (mt == 0 && ks < 3) {   // prefetch next ks's B frags
                    uint32_t r0, r1, r2, r3;
                    LDSM4(r0, r1, r2, r3, Sb + bBase0 + cx[ks + 1]);
                    bfb[cur ^ 1][0][0] = r0; bfb[cur ^ 1][0][1] = r2;
                    bfb[cur ^ 1][1][0] = r1; bfb[cur ^ 1][1][1] = r3;
                    LDSM4(r0, r1, r2, r3, Sb + bBase0 + 2048 + cx[ks + 1]);
                    bfb[cur ^ 1][2][0] = r0; bfb[cur ^ 1][2][1] = r2;
                    bfb[cur ^ 1][3][0] = r1; bfb[cur ^ 1][3][1] = r3;
                }
                {   // prefetch next step's A frag
                    const int step = ks * 4 + mt;
                    if (step < 15) {
                        const int nks = (mt == 3) ? ks + 1 : ks;
                        const int nmt = (mt + 1) & 3;
                        uint32_t* an = a[(step + 1) & 1];
                        LDSM4(an[0], an[1], an[2], an[3],
                              Sb + aBase0 + nmt * 2048 + cx[nks]);
                    }
                }
                const uint32_t* ac = a[mt & 1];   // step&1 == mt&1 (4*ks even)
#pragma unroll
                for (int nt = 0; nt < 4; nt++)
                    MMAF16(acc[mt][nt], ac, bfb[cur][nt][0], bfb[cur][nt][1]);
            }
        }
    }

    // ---------------- epilogue ----------------
#pragma unroll
    for (int mt = 0; mt < 4; mt++) {
#pragma unroll
        for (int nt = 0; nt < 4; nt++) {
            int row = rowBase + wm * 64 + mt * 16 + (lane >> 2);
            int col = colBase + wn * 32 + nt * 8 + (lane & 3) * 2;
            *(float2*)&out[(size_t)row * NDOUT + col] =
                make_float2(acc[mt][nt][0], acc[mt][nt][1]);
            *(float2*)&out[(size_t)(row + 8) * NDOUT + col] =
                make_float2(acc[mt][nt][2], acc[mt][nt][3]);
        }
    }
}

// ---------------- launch ----------------
extern "C" void kernel_launch(void* const* d_in, const int* in_sizes, int n_in,
                              void* d_out, int out_size) {
    const float* x      = (const float*)d_in[0];
    const float* gate   = (const float*)d_in[1];
    const float* W_org  = (const float*)d_in[2];
    const float* W_down = (const float*)d_in[3];
    const float* W_up   = (const float*)d_in[4];
    float* out = (float*)d_out;

    cudaFuncSetAttribute(k_gemm, cudaFuncAttributeMaxDynamicSharedMemorySize, SMEM_TOTAL);
    cudaFuncSetAttribute(k_lx, cudaFuncAttributeMaxDynamicSharedMemorySize, LX_SMEM);

    k_cvt_x<<<(size_t)NM * NDIN / 2048, 256>>>(x);
    k_cvt_w_comb<<<2048 + 512, 256>>>(W_org, gate, W_up);
    k_lx<<<NM / 128, 128, LX_SMEM>>>(W_down);

    dim3 grid(NDOUT / BN, NM / BM);   // (16, 128) = 2048 CTAs
    k_gemm<<<grid, 256, SMEM_TOTAL>>>(out);
}

// round 14
// speedup vs baseline: 1.1925x; 1.0300x over previous
#include <cuda_runtime.h>
#include <cuda_fp16.h>
#include <cstdint>

// ---------------- problem constants ----------------
#define NB 4
#define NS 4096
#define NDIN 2048
#define NDOUT 2048
#define NR 16
#define NE 12
#define NM (NB * NS)  // 16384

// ---------------- GEMM tiling ----------------
#define BM 128
#define BN 128
#define CK 64                    // K per chunk (fp16): 128B rows
#define NCHUNK (NDIN / CK)       // 32
#define NCHTOT (NCHUNK + 1)      // +1 LoRA chunk (K=16 zero-padded to 64)
#define NSTAGE 3

#define PART_SZ 16384                        // 128 rows x 128B
#define OF_B PART_SZ
#define STAGE_SZ (2 * PART_SZ)               // 32768
#define OF_TILE 1024                         // mbarriers live below
#define SMEM_TOTAL (OF_TILE + NSTAGE * STAGE_SZ)   // 99328 (x2 CTAs < 228KB)

// ---------------- scratch (device globals: allocation-free rule) ----------------
__device__ __align__(16) __half g_x16[(size_t)NM * NDIN];
__device__ __align__(16) __half g_w16[(size_t)NDOUT * NDIN];
__device__ __align__(16) __half g_lx16[(size_t)NM * 64];          // cols 16-63 = 0
__device__ __align__(16) __half g_cb16[(size_t)NB * NDOUT * 64];  // cols 16-63 = 0

// ---------------- PTX helpers (plain sm_80+ instructions only) ----------------
__device__ __forceinline__ uint32_t smem_u32(const void* p) {
    uint32_t a;
    asm("{ .reg .u64 t; cvta.to.shared.u64 t, %1; cvt.u32.u64 %0, t; }" : "=r"(a) : "l"(p));
    return a;
}
__device__ __forceinline__ void cp16(uint32_t saddr, const void* gptr) {
    asm volatile("cp.async.cg.shared.global [%0], [%1], 16;"
                 :: "r"(saddr), "l"(__cvta_generic_to_global(gptr)) : "memory");
}
__device__ __forceinline__ void cp_commit() {
    asm volatile("cp.async.commit_group;" ::: "memory");
}
__device__ __forceinline__ void cp_wait1() {
    asm volatile("cp.async.wait_group 1;" ::: "memory");
}
// mbarrier ops (sm_80+; compiled clean for sm_103 in R3)
__device__ __forceinline__ void mbar_init(uint32_t a, uint32_t cnt) {
    asm volatile("mbarrier.init.shared.b64 [%0], %1;" :: "r"(a), "r"(cnt) : "memory");
}
__device__ __forceinline__ void mbar_arrive(uint32_t a) {
    asm volatile("mbarrier.arrive.shared.b64 _, [%0];" :: "r"(a) : "memory");
}
__device__ __forceinline__ void cp_arrive_noinc(uint32_t a) {
    asm volatile("cp.async.mbarrier.arrive.noinc.shared.b64 [%0];" :: "r"(a) : "memory");
}
__device__ __forceinline__ void mbar_wait(uint32_t a, uint32_t parity) {
    asm volatile(
        "{\n\t.reg .pred P;\n\t"
        "WL_%=:\n\t"
        "mbarrier.try_wait.parity.acquire.cta.shared::cta.b64 P, [%0], %1, 0x989680;\n\t"
        "@!P bra WL_%=;\n\t}"
        :: "r"(a), "r"(parity) : "memory");
}
#define LDSM4(r0, r1, r2, r3, addr)                                              \
    asm volatile("ldmatrix.sync.aligned.m8n8.x4.shared.b16 {%0,%1,%2,%3}, [%4];" \
                 : "=r"(r0), "=r"(r1), "=r"(r2), "=r"(r3) : "r"(addr))
#define MMAF16(c, a, b0, b1)                                                  \
    asm volatile("mma.sync.aligned.m16n8k16.row.col.f32.f16.f16.f32 "         \
                 "{%0,%1,%2,%3},{%4,%5,%6,%7},{%8,%9},{%0,%1,%2,%3};"         \
                 : "+f"((c)[0]), "+f"((c)[1]), "+f"((c)[2]), "+f"((c)[3])     \
                 : "r"((a)[0]), "r"((a)[1]), "r"((a)[2]), "r"((a)[3]),        \
                   "r"(b0), "r"(b1))

// 128B-row swizzle (validated since R7): 16B-chunk' = ch ^ (row&7)
__device__ __forceinline__ uint32_t swof(int row, int ch) {
    return (uint32_t)(row * 128 + ((ch ^ (row & 7)) << 4));
}

// ---------------- pre-kernels: fp32 -> fp16 RN conversion ----------------
union H8 { __half2 h[4]; uint4 u; };

__device__ __forceinline__ void cvt8h(const float* src, __half* dst, size_t i) {
    float4 v0 = *(const float4*)(src + i);
    float4 v1 = *(const float4*)(src + i + 4);
    H8 o;
    o.h[0] = __float22half2_rn(make_float2(v0.x, v0.y));
    o.h[1] = __float22half2_rn(make_float2(v0.z, v0.w));
    o.h[2] = __float22half2_rn(make_float2(v1.x, v1.y));
    o.h[3] = __float22half2_rn(make_float2(v1.z, v1.w));
    *(uint4*)(dst + i) = o.u;
}
__global__ void k_cvt_x(const float* __restrict__ x) {
    size_t i = ((size_t)blockIdx.x * 256 + threadIdx.x) * 8;
    cvt8h(x, g_x16, i);
}
__global__ void k_cvt_w_comb(const float* __restrict__ W_org,
                             const float* __restrict__ gate,
                             const float* __restrict__ W_up) {
    if (blockIdx.x < 2048) {
        size_t i = ((size_t)blockIdx.x * 256 + threadIdx.x) * 8;
        cvt8h(W_org, g_w16, i);
    } else {
        int idx = (blockIdx.x - 2048) * 256 + threadIdx.x;
        if (idx >= NB * NDOUT * NR) return;
        int b = idx / (NDOUT * NR);
        int orr = idx - b * (NDOUT * NR);
        int o = orr >> 4, r = orr & 15;
        float s = 0.f;
#pragma unroll
        for (int e = 0; e < NE; e++)
            s += __ldg(&gate[b * NE + e]) * __ldg(&W_up[(size_t)e * NDOUT * NR + orr]);
        size_t off = ((size_t)b * NDOUT + o) * 64;
        g_cb16[off + r] = __float2half_rn(s);
        if (r < 6) {  // zero cols 16..63
            uint4 z = make_uint4(0, 0, 0, 0);
            *(uint4*)&g_cb16[off + 16 + r * 8] = z;
        }
    }
}

// ---------------- k_lx: lx[m,0:16] = x @ W_down^T via fp16 mma ----------------
#define LXW 65536                        // 16 n-rows x 2048 k x 2B (fp16 W_down)
#define LX_STG 16384                     // 128 rows x 64 k x 2B (128B rows)
#define LX_SMEM (LXW + 3 * LX_STG)       // 114688
#define LXCK 64
#define LXNCH (NDIN / LXCK)              // 32

__device__ __forceinline__ void lx_issue(uint32_t sb, int s, int c, int rowBase, int tid) {
    uint32_t xs = sb + LXW + s * LX_STG;
#pragma unroll
    for (int j = 0; j < 8; j++) {
        int g = tid + 128 * j;
        int row = g >> 3, ch = g & 7;
        cp16(xs + swof(row, ch),
             g_x16 + (size_t)(rowBase + row) * NDIN + c * LXCK + ch * 8);
    }
}

__global__ void __launch_bounds__(128, 1) k_lx(const float* __restrict__ Wd) {
    extern __shared__ char sm[];
    const uint32_t sb = smem_u32(sm);
    const int tid = threadIdx.x;
    const int w = tid >> 5, lane = tid & 31;
    const int rowBase = blockIdx.x * 128;
    const int lr = lane & 15, lc = lane >> 4;

    for (int idx = tid; idx < 16 * 256; idx += 128) {
        int n = idx >> 8, ch = idx & 255;
        const float* s8 = Wd + (size_t)n * NDIN + ch * 8;
        float4 v0 = *(const float4*)s8;
        float4 v1 = *(const float4*)(s8 + 4);
        H8 o;
        o.h[0] = __float22half2_rn(make_float2(v0.x, v0.y));
        o.h[1] = __float22half2_rn(make_float2(v0.z, v0.w));
        o.h[2] = __float22half2_rn(make_float2(v1.x, v1.y));
        o.h[3] = __float22half2_rn(make_float2(v1.z, v1.w));
        *(uint4*)(sm + n * 4096 + ((ch ^ (n & 7)) << 4)) = o.u;
    }

    float acc[2][2][4];
#pragma unroll
    for (int i = 0; i < 2; i++)
#pragma unroll
        for (int j = 0; j < 2; j++)
#pragma unroll
            for (int q = 0; q < 4; q++) acc[i][j][q] = 0.f;

    lx_issue(sb, 0, 0, rowBase, tid); cp_commit();
    lx_issue(sb, 1, 1, rowBase, tid); cp_commit();

    for (int c = 0; c < LXNCH; c++) {
        cp_wait1();
        __syncthreads();
        if (c + 2 < LXNCH) lx_issue(sb, (c + 2) % 3, c + 2, rowBase, tid);
        cp_commit();
        const uint32_t xs = sb + LXW + (c % 3) * LX_STG;
#pragma unroll
        for (int ks = 0; ks < 4; ks++) {
            int K = c * 4 + ks;
            uint32_t chB = (uint32_t)(2 * K + lc);
            uint32_t r0, r1, r2, r3;
            LDSM4(r0, r1, r2, r3, sb + lr * 4096 + ((chB ^ (lr & 7)) << 4));
            uint32_t bf0[2] = {r0, r2}, bf1[2] = {r1, r3};
#pragma unroll
            for (int mt = 0; mt < 2; mt++) {
                int row = w * 32 + mt * 16 + lr;
                uint32_t ch = (uint32_t)(ks * 2 + lc);
                uint32_t a[4];
                LDSM4(a[0], a[1], a[2], a[3],
                      xs + row * 128 + ((ch ^ (row & 7)) << 4));
                MMAF16(acc[mt][0], a, bf0[0], bf0[1]);
                MMAF16(acc[mt][1], a, bf1[0], bf1[1]);
            }
        }
        __syncthreads();
    }

#pragma unroll
    for (int mt = 0; mt < 2; mt++) {
        int row = rowBase + w * 32 + mt * 16 + (lane >> 2);
#pragma unroll
        for (int nt = 0; nt < 2; nt++) {
            int col = nt * 8 + (lane & 3) * 2;
            *(__half2*)&g_lx16[(size_t)row * 64 + col] =
                __float22half2_rn(make_float2(acc[mt][nt][0], acc[mt][nt][1]));
            *(__half2*)&g_lx16[(size_t)(row + 8) * 64 + col] =
                __float22half2_rn(make_float2(acc[mt][nt][2], acc[mt][nt][3]));
        }
    }
    {
        int m = rowBase + tid;
        uint4 z = make_uint4(0, 0, 0, 0);
#pragma unroll
        for (int zz = 0; zz < 6; zz++)
            *(uint4*)&g_lx16[(size_t)m * 64 + 16 + zz * 8] = z;
    }
}

// ---------------- main GEMM: fp16, mbarrier async pipeline ----------------
__global__ void __launch_bounds__(256, 2) k_gemm(float* __restrict__ out) {
    extern __shared__ char smem[];
    const uint32_t sb0 = smem_u32(smem);
    const int tid = threadIdx.x;
    const int wid = tid >> 5, lane = tid & 31;
    const int wm = wid >> 2, wn = wid & 3;      // warp tile 64x32
    const int rowBase = blockIdx.y * BM;
    const int colBase = blockIdx.x * BN;
    const int b = blockIdx.y >> 5;              // NS/BM = 32 row-blocks per batch
    const int lr = lane & 15, lc = lane >> 4;
    const uint32_t sw7 = (uint32_t)(lr & 7);

    // mbarriers: full[s] at s*8, empty[s] at 24 + s*8
    const uint32_t mbF = sb0, mbE = sb0 + 24;
    if (tid == 0) {
#pragma unroll
        for (int s = 0; s < NSTAGE; s++) {
            mbar_init(mbF + s * 8, 256);   // one noinc cp-arrival per thread
            mbar_init(mbE + s * 8, 8);     // one arrival per warp
        }
    }
    __syncthreads();   // sole full barrier: mbarrier init visibility

    // fragment bases
    const uint32_t aBase0 = (uint32_t)((wm * 64 + lr) * 128);
    const uint32_t bBase0 = OF_B + (uint32_t)((wn * 32 + lr) * 128);
    uint32_t cx[4];
#pragma unroll
    for (int ks = 0; ks < 4; ks++)
        cx[ks] = ((uint32_t)(2 * ks + lc) ^ sw7) << 4;

    // loader
    const int lrow = tid >> 3, lch = tid & 7;   // lrow 0..31
    const uint32_t so0 = OF_TILE + swof(lrow, lch);  // + j*4096 (row&7 invariant)
    const __half* aG = g_x16 + (size_t)(rowBase + lrow) * NDIN + lch * 8;
    const __half* bG = g_w16 + (size_t)(colBase + lrow) * NDIN + lch * 8;
    const __half* aL = g_lx16 + (size_t)(rowBase + lrow) * 64 + lch * 8;
    const __half* bL = g_cb16 + ((size_t)b * NDOUT + colBase + lrow) * 64 + lch * 8;

    float acc[4][4][4];
#pragma unroll
    for (int i = 0; i < 4; i++)
#pragma unroll
        for (int j = 0; j < 4; j++)
#pragma unroll
            for (int q = 0; q < 4; q++) acc[i][j][q] = 0.f;

#pragma unroll
    for (int p = 0; p < 2; p++) {   // prologue: chunks 0,1 (slots fresh, no wait)
        uint32_t s = sb0 + p * STAGE_SZ;
#pragma unroll
        for (int j = 0; j < 4; j++) {
            cp16(s + so0 + j * 4096, aG + p * CK + (size_t)j * 32 * NDIN);
            cp16(s + OF_B + so0 + j * 4096, bG + p * CK + (size_t)j * 32 * NDIN);
        }
        cp_arrive_noinc(mbF + p * 8);
    }

    int c_s = 0, c_p = 0;          // consumer cursor
    int p_s = 2, p_p = 1;          // producer cursor (flip-phase: first waits pass)
    for (int kc = 0; kc < NCHTOT; kc++) {
        // ---- produce chunk kc+2 ----
        const int nk = kc + 2;
        if (nk < NCHTOT) {
            mbar_wait(mbE + p_s * 8, (uint32_t)p_p);
            uint32_t s = sb0 + p_s * STAGE_SZ;
            if (nk < NCHUNK) {
#pragma unroll
                for (int j = 0; j < 4; j++) {
                    cp16(s + so0 + j * 4096, aG + nk * CK + (size_t)j * 32 * NDIN);
                    cp16(s + OF_B + so0 + j * 4096, bG + nk * CK + (size_t)j * 32 * NDIN);
                }
            } else {  // LoRA chunk: rows of 64 fp16 = 128B
#pragma unroll
                for (int j = 0; j < 4; j++) {
                    cp16(s + so0 + j * 4096, aL + (size_t)j * 32 * 64);
                    cp16(s + OF_B + so0 + j * 4096, bL + (size_t)j * 32 * 64);
                }
            }
            cp_arrive_noinc(mbF + p_s * 8);
            if (++p_s == NSTAGE) { p_s = 0; p_p ^= 1; }
        }

        // ---- consume chunk kc ----
        mbar_wait(mbF + c_s * 8, (uint32_t)c_p);
        const uint32_t Sb = sb0 + OF_TILE + c_s * STAGE_SZ;

        uint32_t bfb[2][4][2];     // B frags, double-buffered by ks parity
        uint32_t a[2][4];          // A frags, double-buffered by step parity
        {
            uint32_t r0, r1, r2, r3;
            LDSM4(r0, r1, r2, r3, Sb + bBase0 - OF_TILE + OF_TILE + cx[0]);
            bfb[0][0][0] = r0; bfb[0][0][1] = r2;
            bfb[0][1][0] = r1; bfb[0][1][1] = r3;
            LDSM4(r0, r1, r2, r3, Sb + bBase0 + 2048 + cx[0]);
            bfb[0][2][0] = r0; bfb[0][2][1] = r2;
            bfb[0][3][0] = r1; bfb[0][3][1] = r3;
            LDSM4(a[0][0], a[0][1], a[0][2], a[0][3], Sb + aBase0 + cx[0]);
        }
#pragma unroll
        for (int ks = 0; ks < 4; ks++) {
            const int cur = ks & 1;
#pragma unroll
            for (int mt = 0; mt < 4; mt++) {
                if (mt == 0 && ks < 3) {   // prefetch next ks's B frags
                    uint32_t r0, r1, r2, r3;
                    LDSM4(r0, r1, r2, r3, Sb + bBase0 + cx[ks + 1]);
                    bfb[cur ^ 1][0][0] = r0; bfb[cur ^ 1][0][1] = r2;
                    bfb[cur ^ 1][1][0] = r1; bfb[cur ^ 1][1][1] = r3;
                    LDSM4(r0, r1, r2, r3, Sb + bBase0 + 2048 + cx[ks + 1]);
                    bfb[cur ^ 1][2][0] = r0; bfb[cur ^ 1][2][1] = r2;
                    bfb[cur ^ 1][3][0] = r1; bfb[cur ^ 1][3][1] = r3;
                }
                {   // prefetch next step's A frag
                    const int step = ks * 4 + mt;
                    if (step < 15) {
                        const int nks = (mt == 3) ? ks + 1 : ks;
                        const int nmt = (mt + 1) & 3;
                        uint32_t* an = a[(step + 1) & 1];
                        LDSM4(an[0], an[1], an[2], an[3],
                              Sb + aBase0 + nmt * 2048 + cx[nks]);
                    }
                }
                const uint32_t* ac = a[mt & 1];
#pragma unroll
                for (int nt = 0; nt < 4; nt++)
                    MMAF16(acc[mt][nt], ac, bfb[cur][nt][0], bfb[cur][nt][1]);
            }
        }
        // all LDSMs for this chunk done (ldmatrix.sync is warp-converged)
        if (lane == 0) mbar_arrive(mbE + c_s * 8);
        if (++c_s == NSTAGE) { c_s = 0; c_p ^= 1; }
    }

    // ---------------- epilogue ----------------
#pragma unroll
    for (int mt = 0; mt < 4; mt++) {
#pragma unroll
        for (int nt = 0; nt < 4; nt++) {
            int row = rowBase + wm * 64 + mt * 16 + (lane >> 2);
            int col = colBase + wn * 32 + nt * 8 + (lane & 3) * 2;
            *(float2*)&out[(size_t)row * NDOUT + col] =
                make_float2(acc[mt][nt][0], acc[mt][nt][1]);
            *(float2*)&out[(size_t)(row + 8) * NDOUT + col] =
                make_float2(acc[mt][nt][2], acc[mt][nt][3]);
        }
    }
}

// ---------------- launch ----------------
extern "C" void kernel_launch(void* const* d_in, const int* in_sizes, int n_in,
                              void* d_out, int out_size) {
    const float* x      = (const float*)d_in[0];
    const float* gate   = (const float*)d_in[1];
    const float* W_org  = (const float*)d_in[2];
    const float* W_down = (const float*)d_in[3];
    const float* W_up   = (const float*)d_in[4];
    float* out = (float*)d_out;

    cudaFuncSetAttribute(k_gemm, cudaFuncAttributeMaxDynamicSharedMemorySize, SMEM_TOTAL);
    cudaFuncSetAttribute(k_lx, cudaFuncAttributeMaxDynamicSharedMemorySize, LX_SMEM);

    k_cvt_x<<<(size_t)NM * NDIN / 2048, 256>>>(x);
    k_cvt_w_comb<<<2048 + 512, 256>>>(W_org, gate, W_up);
    k_lx<<<NM / 128, 128, LX_SMEM>>>(W_down);

    dim3 grid(NDOUT / BN, NM / BM);   // (16, 128) = 2048 CTAs
    k_gemm<<<grid, 256, SMEM_TOTAL>>>(out);
}

// round 15
// speedup vs baseline: 1.2268x; 1.0288x over previous
#include <cuda_runtime.h>
#include <cuda_fp16.h>
#include <cstdint>

// ---------------- problem constants ----------------
#define NB 4
#define NS 4096
#define NDIN 2048
#define NDOUT 2048
#define NR 16
#define NE 12
#define NM (NB * NS)  // 16384

// ---------------- GEMM tiling ----------------
#define BM 128
#define BN 128
#define CK 64                    // K per chunk (fp16): 128B rows
#define NCHUNK (NDIN / CK)       // 32
#define NCHTOT (NCHUNK + 1)      // +1 LoRA chunk (K=16 zero-padded to 64)
#define NSTAGE 3

#define PART_SZ 16384                        // 128 rows x 128B
#define OF_B PART_SZ
#define STAGE_SZ (2 * PART_SZ)               // 32768
#define OF_TILE 1024                         // mbarriers live below
#define SMEM_TOTAL (OF_TILE + NSTAGE * STAGE_SZ)   // 99328 (x2 CTAs < 228KB)

// ---------------- scratch (device globals: allocation-free rule) ----------------
__device__ __align__(16) __half g_x16[(size_t)NM * NDIN];
__device__ __align__(16) __half g_w16[(size_t)NDOUT * NDIN];
__device__ __align__(16) __half g_lx16[(size_t)NM * 64];          // cols 16-63 = 0
__device__ __align__(16) __half g_cb16[(size_t)NB * NDOUT * 64];  // cols 16-63 = 0

// ---------------- PTX helpers (plain sm_80+ instructions only) ----------------
__device__ __forceinline__ uint32_t smem_u32(const void* p) {
    uint32_t a;
    asm("{ .reg .u64 t; cvta.to.shared.u64 t, %1; cvt.u32.u64 %0, t; }" : "=r"(a) : "l"(p));
    return a;
}
__device__ __forceinline__ void cp16(uint32_t saddr, const void* gptr) {
    asm volatile("cp.async.cg.shared.global [%0], [%1], 16;"
                 :: "r"(saddr), "l"(__cvta_generic_to_global(gptr)) : "memory");
}
__device__ __forceinline__ void cp_commit() {
    asm volatile("cp.async.commit_group;" ::: "memory");
}
__device__ __forceinline__ void cp_wait1() {
    asm volatile("cp.async.wait_group 1;" ::: "memory");
}
// mbarrier ops (protocol validated end-to-end in R14)
__device__ __forceinline__ void mbar_init(uint32_t a, uint32_t cnt) {
    asm volatile("mbarrier.init.shared.b64 [%0], %1;" :: "r"(a), "r"(cnt) : "memory");
}
__device__ __forceinline__ void mbar_arrive(uint32_t a) {
    asm volatile("mbarrier.arrive.shared.b64 _, [%0];" :: "r"(a) : "memory");
}
__device__ __forceinline__ void cp_arrive_noinc(uint32_t a) {
    asm volatile("cp.async.mbarrier.arrive.noinc.shared.b64 [%0];" :: "r"(a) : "memory");
}
__device__ __forceinline__ void mbar_wait(uint32_t a, uint32_t parity) {
    asm volatile(
        "{\n\t.reg .pred P;\n\t"
        "WL_%=:\n\t"
        "mbarrier.try_wait.parity.acquire.cta.shared::cta.b64 P, [%0], %1, 0x989680;\n\t"
        "@!P bra WL_%=;\n\t}"
        :: "r"(a), "r"(parity) : "memory");
}
#define LDSM4(r0, r1, r2, r3, addr)                                              \
    asm volatile("ldmatrix.sync.aligned.m8n8.x4.shared.b16 {%0,%1,%2,%3}, [%4];" \
                 : "=r"(r0), "=r"(r1), "=r"(r2), "=r"(r3) : "r"(addr))
#define MMAF16(c, a, b0, b1)                                                  \
    asm volatile("mma.sync.aligned.m16n8k16.row.col.f32.f16.f16.f32 "         \
                 "{%0,%1,%2,%3},{%4,%5,%6,%7},{%8,%9},{%0,%1,%2,%3};"         \
                 : "+f"((c)[0]), "+f"((c)[1]), "+f"((c)[2]), "+f"((c)[3])     \
                 : "r"((a)[0]), "r"((a)[1]), "r"((a)[2]), "r"((a)[3]),        \
                   "r"(b0), "r"(b1))

// 128B-row swizzle (validated since R7): 16B-chunk' = ch ^ (row&7)
__device__ __forceinline__ uint32_t swof(int row, int ch) {
    return (uint32_t)(row * 128 + ((ch ^ (row & 7)) << 4));
}

// ---------------- merged pre-kernel: cvt x + cvt W + gate-combine ----------------
union H8 { __half2 h[4]; uint4 u; };

__device__ __forceinline__ void cvt8h(const float* src, __half* dst, size_t i) {
    float4 v0 = *(const float4*)(src + i);
    float4 v1 = *(const float4*)(src + i + 4);
    H8 o;
    o.h[0] = __float22half2_rn(make_float2(v0.x, v0.y));
    o.h[1] = __float22half2_rn(make_float2(v0.z, v0.w));
    o.h[2] = __float22half2_rn(make_float2(v1.x, v1.y));
    o.h[3] = __float22half2_rn(make_float2(v1.z, v1.w));
    *(uint4*)(dst + i) = o.u;
}
// blocks [0,16384): cvt x; [16384,18432): cvt W_org; [18432,18944): combine
__global__ void k_cvt(const float* __restrict__ x,
                      const float* __restrict__ W_org,
                      const float* __restrict__ gate,
                      const float* __restrict__ W_up) {
    int bb = blockIdx.x;
    if (bb < 16384) {
        size_t i = ((size_t)bb * 256 + threadIdx.x) * 8;
        cvt8h(x, g_x16, i);
    } else if (bb < 18432) {
        size_t i = ((size_t)(bb - 16384) * 256 + threadIdx.x) * 8;
        cvt8h(W_org, g_w16, i);
    } else {
        int idx = (bb - 18432) * 256 + threadIdx.x;
        if (idx >= NB * NDOUT * NR) return;
        int b = idx / (NDOUT * NR);
        int orr = idx - b * (NDOUT * NR);
        int o = orr >> 4, r = orr & 15;
        float s = 0.f;
#pragma unroll
        for (int e = 0; e < NE; e++)
            s += __ldg(&gate[b * NE + e]) * __ldg(&W_up[(size_t)e * NDOUT * NR + orr]);
        size_t off = ((size_t)b * NDOUT + o) * 64;
        g_cb16[off + r] = __float2half_rn(s);
        if (r < 6) {  // zero cols 16..63
            uint4 z = make_uint4(0, 0, 0, 0);
            *(uint4*)&g_cb16[off + 16 + r * 8] = z;
        }
    }
}

// ---------------- k_lx: lx[m,0:16] = x @ W_down^T via fp16 mma ----------------
#define LXW 65536                        // 16 n-rows x 2048 k x 2B (fp16 W_down)
#define LX_STG 16384                     // 128 rows x 64 k x 2B (128B rows)
#define LX_SMEM (LXW + 3 * LX_STG)       // 114688
#define LXCK 64
#define LXNCH (NDIN / LXCK)              // 32

__device__ __forceinline__ void lx_issue(uint32_t sb, int s, int c, int rowBase, int tid) {
    uint32_t xs = sb + LXW + s * LX_STG;
#pragma unroll
    for (int j = 0; j < 8; j++) {
        int g = tid + 128 * j;
        int row = g >> 3, ch = g & 7;
        cp16(xs + swof(row, ch),
             g_x16 + (size_t)(rowBase + row) * NDIN + c * LXCK + ch * 8);
    }
}

__global__ void __launch_bounds__(128, 1) k_lx(const float* __restrict__ Wd) {
    extern __shared__ char sm[];
    const uint32_t sb = smem_u32(sm);
    const int tid = threadIdx.x;
    const int w = tid >> 5, lane = tid & 31;
    const int rowBase = blockIdx.x * 128;
    const int lr = lane & 15, lc = lane >> 4;

    for (int idx = tid; idx < 16 * 256; idx += 128) {
        int n = idx >> 8, ch = idx & 255;
        const float* s8 = Wd + (size_t)n * NDIN + ch * 8;
        float4 v0 = *(const float4*)s8;
        float4 v1 = *(const float4*)(s8 + 4);
        H8 o;
        o.h[0] = __float22half2_rn(make_float2(v0.x, v0.y));
        o.h[1] = __float22half2_rn(make_float2(v0.z, v0.w));
        o.h[2] = __float22half2_rn(make_float2(v1.x, v1.y));
        o.h[3] = __float22half2_rn(make_float2(v1.z, v1.w));
        *(uint4*)(sm + n * 4096 + ((ch ^ (n & 7)) << 4)) = o.u;
    }

    float acc[2][2][4];
#pragma unroll
    for (int i = 0; i < 2; i++)
#pragma unroll
        for (int j = 0; j < 2; j++)
#pragma unroll
            for (int q = 0; q < 4; q++) acc[i][j][q] = 0.f;

    lx_issue(sb, 0, 0, rowBase, tid); cp_commit();
    lx_issue(sb, 1, 1, rowBase, tid); cp_commit();

    for (int c = 0; c < LXNCH; c++) {
        cp_wait1();
        __syncthreads();
        if (c + 2 < LXNCH) lx_issue(sb, (c + 2) % 3, c + 2, rowBase, tid);
        cp_commit();
        const uint32_t xs = sb + LXW + (c % 3) * LX_STG;
#pragma unroll
        for (int ks = 0; ks < 4; ks++) {
            int K = c * 4 + ks;
            uint32_t chB = (uint32_t)(2 * K + lc);
            uint32_t r0, r1, r2, r3;
            LDSM4(r0, r1, r2, r3, sb + lr * 4096 + ((chB ^ (lr & 7)) << 4));
            uint32_t bf0[2] = {r0, r2}, bf1[2] = {r1, r3};
#pragma unroll
            for (int mt = 0; mt < 2; mt++) {
                int row = w * 32 + mt * 16 + lr;
                uint32_t ch = (uint32_t)(ks * 2 + lc);
                uint32_t a[4];
                LDSM4(a[0], a[1], a[2], a[3],
                      xs + row * 128 + ((ch ^ (row & 7)) << 4));
                MMAF16(acc[mt][0], a, bf0[0], bf0[1]);
                MMAF16(acc[mt][1], a, bf1[0], bf1[1]);
            }
        }
        __syncthreads();
    }

#pragma unroll
    for (int mt = 0; mt < 2; mt++) {
        int row = rowBase + w * 32 + mt * 16 + (lane >> 2);
#pragma unroll
        for (int nt = 0; nt < 2; nt++) {
            int col = nt * 8 + (lane & 3) * 2;
            *(__half2*)&g_lx16[(size_t)row * 64 + col] =
                __float22half2_rn(make_float2(acc[mt][nt][0], acc[mt][nt][1]));
            *(__half2*)&g_lx16[(size_t)(row + 8) * 64 + col] =
                __float22half2_rn(make_float2(acc[mt][nt][2], acc[mt][nt][3]));
        }
    }
    {
        int m = rowBase + tid;
        uint4 z = make_uint4(0, 0, 0, 0);
#pragma unroll
        for (int zz = 0; zz < 6; zz++)
            *(uint4*)&g_lx16[(size_t)m * 64 + 16 + zz * 8] = z;
    }
}

// ---------------- main GEMM: fp16, mbarrier pipeline, consume-then-produce ----------------
__global__ void __launch_bounds__(256, 2) k_gemm(float* __restrict__ out) {
    extern __shared__ char smem[];
    const uint32_t sb0 = smem_u32(smem);
    const int tid = threadIdx.x;
    const int wid = tid >> 5, lane = tid & 31;
    const int wm = wid >> 2, wn = wid & 3;      // warp tile 64x32
    const int rowBase = blockIdx.y * BM;
    const int colBase = blockIdx.x * BN;
    const int b = blockIdx.y >> 5;              // NS/BM = 32 row-blocks per batch
    const int lr = lane & 15, lc = lane >> 4;
    const uint32_t sw7 = (uint32_t)(lr & 7);

    // mbarriers: full[s] at s*8, empty[s] at 24 + s*8
    const uint32_t mbF = sb0, mbE = sb0 + 24;
    if (tid == 0) {
#pragma unroll
        for (int s = 0; s < NSTAGE; s++) {
            mbar_init(mbF + s * 8, 256);
            mbar_init(mbE + s * 8, 8);
        }
    }
    __syncthreads();

    const uint32_t aBase0 = (uint32_t)((wm * 64 + lr) * 128);
    const uint32_t bBase0 = OF_B + (uint32_t)((wn * 32 + lr) * 128);
    uint32_t cx[4];
#pragma unroll
    for (int ks = 0; ks < 4; ks++)
        cx[ks] = ((uint32_t)(2 * ks + lc) ^ sw7) << 4;

    const int lrow = tid >> 3, lch = tid & 7;
    const uint32_t so0 = OF_TILE + swof(lrow, lch);
    const __half* aG = g_x16 + (size_t)(rowBase + lrow) * NDIN + lch * 8;
    const __half* bG = g_w16 + (size_t)(colBase + lrow) * NDIN + lch * 8;
    const __half* aL = g_lx16 + (size_t)(rowBase + lrow) * 64 + lch * 8;
    const __half* bL = g_cb16 + ((size_t)b * NDOUT + colBase + lrow) * 64 + lch * 8;

    float acc[4][4][4];
#pragma unroll
    for (int i = 0; i < 4; i++)
#pragma unroll
        for (int j = 0; j < 4; j++)
#pragma unroll
            for (int q = 0; q < 4; q++) acc[i][j][q] = 0.f;

#pragma unroll
    for (int p = 0; p < 2; p++) {   // prologue: chunks 0,1
        uint32_t s = sb0 + p * STAGE_SZ;
#pragma unroll
        for (int j = 0; j < 4; j++) {
            cp16(s + so0 + j * 4096, aG + p * CK + (size_t)j * 32 * NDIN);
            cp16(s + OF_B + so0 + j * 4096, bG + p * CK + (size_t)j * 32 * NDIN);
        }
        cp_arrive_noinc(mbF + p * 8);
    }

    int c_s = 0, c_p = 0;          // consumer cursor
    int p_s = 2, p_p = 1;          // producer cursor (flip-phase; R14-validated)
    for (int kc = 0; kc < NCHTOT; kc++) {
        // ---- consume chunk kc ----
        mbar_wait(mbF + c_s * 8, (uint32_t)c_p);
        const uint32_t Sb = sb0 + OF_TILE + c_s * STAGE_SZ;

        uint32_t bfb[2][4][2];     // B frags, double-buffered by ks parity
        uint32_t a[3][4];          // A frags, triple-buffered (prefetch dist 2)
        {
            uint32_t r0, r1, r2, r3;
            LDSM4(r0, r1, r2, r3, Sb + bBase0 + cx[0]);
            bfb[0][0][0] = r0; bfb[0][0][1] = r2;
            bfb[0][1][0] = r1; bfb[0][1][1] = r3;
            LDSM4(r0, r1, r2, r3, Sb + bBase0 + 2048 + cx[0]);
            bfb[0][2][0] = r0; bfb[0][2][1] = r2;
            bfb[0][3][0] = r1; bfb[0][3][1] = r3;
            LDSM4(a[0][0], a[0][1], a[0][2], a[0][3], Sb + aBase0 + cx[0]);
            LDSM4(a[1][0], a[1][1], a[1][2], a[1][3], Sb + aBase0 + 2048 + cx[0]);
        }
#pragma unroll
        for (int ks = 0; ks < 4; ks++) {
            const int cur = ks & 1;
#pragma unroll
            for (int mt = 0; mt < 4; mt++) {
                const int step = ks * 4 + mt;
                if (mt == 0 && ks < 3) {   // B prefetch, first half
                    uint32_t r0, r1, r2, r3;
                    LDSM4(r0, r1, r2, r3, Sb + bBase0 + cx[ks + 1]);
                    bfb[cur ^ 1][0][0] = r0; bfb[cur ^ 1][0][1] = r2;
                    bfb[cur ^ 1][1][0] = r1; bfb[cur ^ 1][1][1] = r3;
                }
                if (mt == 1 && ks < 3) {   // B prefetch, second half
                    uint32_t r0, r1, r2, r3;
                    LDSM4(r0, r1, r2, r3, Sb + bBase0 + 2048 + cx[ks + 1]);
                    bfb[cur ^ 1][2][0] = r0; bfb[cur ^ 1][2][1] = r2;
                    bfb[cur ^ 1][3][0] = r1; bfb[cur ^ 1][3][1] = r3;
                }
                if (step + 2 < 16) {       // A prefetch, distance 2
                    const int ns = step + 2;
                    uint32_t* an = a[ns % 3];
                    LDSM4(an[0], an[1], an[2], an[3],
                          Sb + aBase0 + (ns & 3) * 2048 + cx[ns >> 2]);
                }
                const uint32_t* ac = a[step % 3];
#pragma unroll
                for (int nt = 0; nt < 4; nt++)
                    MMAF16(acc[mt][nt], ac, bfb[cur][nt][0], bfb[cur][nt][1]);
            }
        }
        if (lane == 0) mbar_arrive(mbE + c_s * 8);
        if (++c_s == NSTAGE) { c_s = 0; c_p ^= 1; }

        // ---- produce chunk kc+2 (after consuming: extra slack on empty-wait) ----
        const int nk = kc + 2;
        if (nk < NCHTOT) {
            mbar_wait(mbE + p_s * 8, (uint32_t)p_p);
            uint32_t s = sb0 + p_s * STAGE_SZ;
            if (nk < NCHUNK) {
#pragma unroll
                for (int j = 0; j < 4; j++) {
                    cp16(s + so0 + j * 4096, aG + nk * CK + (size_t)j * 32 * NDIN);
                    cp16(s + OF_B + so0 + j * 4096, bG + nk * CK + (size_t)j * 32 * NDIN);
                }
            } else {  // LoRA chunk: rows of 64 fp16 = 128B
#pragma unroll
                for (int j = 0; j < 4; j++) {
                    cp16(s + so0 + j * 4096, aL + (size_t)j * 32 * 64);
                    cp16(s + OF_B + so0 + j * 4096, bL + (size_t)j * 32 * 64);
                }
            }
            cp_arrive_noinc(mbF + p_s * 8);
            if (++p_s == NSTAGE) { p_s = 0; p_p ^= 1; }
        }
    }

    // ---------------- epilogue ----------------
#pragma unroll
    for (int mt = 0; mt < 4; mt++) {
#pragma unroll
        for (int nt = 0; nt < 4; nt++) {
            int row = rowBase + wm * 64 + mt * 16 + (lane >> 2);
            int col = colBase + wn * 32 + nt * 8 + (lane & 3) * 2;
            *(float2*)&out[(size_t)row * NDOUT + col] =
                make_float2(acc[mt][nt][0], acc[mt][nt][1]);
            *(float2*)&out[(size_t)(row + 8) * NDOUT + col] =
                make_float2(acc[mt][nt][2], acc[mt][nt][3]);
        }
    }
}

// ---------------- launch ----------------
extern "C" void kernel_launch(void* const* d_in, const int* in_sizes, int n_in,
                              void* d_out, int out_size) {
    const float* x      = (const float*)d_in[0];
    const float* gate   = (const float*)d_in[1];
    const float* W_org  = (const float*)d_in[2];
    const float* W_down = (const float*)d_in[3];
    const float* W_up   = (const float*)d_in[4];
    float* out = (float*)d_out;

    cudaFuncSetAttribute(k_gemm, cudaFuncAttributeMaxDynamicSharedMemorySize, SMEM_TOTAL);
    cudaFuncSetAttribute(k_lx, cudaFuncAttributeMaxDynamicSharedMemorySize, LX_SMEM);

    k_cvt<<<16384 + 2048 + 512, 256>>>(x, W_org, gate, W_up);
    k_lx<<<NM / 128, 128, LX_SMEM>>>(W_down);

    dim3 grid(NDOUT / BN, NM / BM);   // (16, 128) = 2048 CTAs
    k_gemm<<<grid, 256, SMEM_TOTAL>>>(out);
}

// round 16
// speedup vs baseline: 1.2281x; 1.0011x over previous
#include <cuda_runtime.h>
#include <cuda_fp16.h>
#include <cstdint>

// ---------------- problem constants ----------------
#define NB 4
#define NS 4096
#define NDIN 2048
#define NDOUT 2048
#define NR 16
#define NE 12
#define NM (NB * NS)  // 16384

// ---------------- GEMM tiling ----------------
#define BM 128
#define BN 128
#define CK 64                    // K per chunk (fp16): 128B rows
#define NCHUNK (NDIN / CK)       // 32
#define NCHTOT (NCHUNK + 1)      // +1 LoRA chunk (K=16 zero-padded to 64)
#define NSTAGE 3

#define PART_SZ 16384                        // 128 rows x 128B
#define OF_B PART_SZ
#define STAGE_SZ (2 * PART_SZ)               // 32768
#define OF_TILE 1024                         // mbarriers live below
#define SMEM_TOTAL (OF_TILE + NSTAGE * STAGE_SZ)   // 99328 (x2 CTAs < 228KB)

// ---------------- scratch (device globals: allocation-free rule) ----------------
__device__ __align__(16) __half g_x16[(size_t)NM * NDIN];
__device__ __align__(16) __half g_w16[(size_t)NDOUT * NDIN];
__device__ __align__(16) __half g_lx16[(size_t)NM * 64];          // cols 16-63 = 0
__device__ __align__(16) __half g_cb16[(size_t)NB * NDOUT * 64];  // cols 16-63 = 0

// ---------------- PTX helpers (plain sm_80+ instructions only) ----------------
__device__ __forceinline__ uint32_t smem_u32(const void* p) {
    uint32_t a;
    asm("{ .reg .u64 t; cvta.to.shared.u64 t, %1; cvt.u32.u64 %0, t; }" : "=r"(a) : "l"(p));
    return a;
}
__device__ __forceinline__ void cp16(uint32_t saddr, const void* gptr) {
    asm volatile("cp.async.cg.shared.global [%0], [%1], 16;"
                 :: "r"(saddr), "l"(__cvta_generic_to_global(gptr)) : "memory");
}
__device__ __forceinline__ void cp_commit() {
    asm volatile("cp.async.commit_group;" ::: "memory");
}
__device__ __forceinline__ void cp_wait1() {
    asm volatile("cp.async.wait_group 1;" ::: "memory");
}
// mbarrier ops (protocol validated end-to-end in R14/R15)
__device__ __forceinline__ void mbar_init(uint32_t a, uint32_t cnt) {
    asm volatile("mbarrier.init.shared.b64 [%0], %1;" :: "r"(a), "r"(cnt) : "memory");
}
__device__ __forceinline__ void mbar_arrive(uint32_t a) {
    asm volatile("mbarrier.arrive.shared.b64 _, [%0];" :: "r"(a) : "memory");
}
__device__ __forceinline__ void cp_arrive_noinc(uint32_t a) {
    asm volatile("cp.async.mbarrier.arrive.noinc.shared.b64 [%0];" :: "r"(a) : "memory");
}
__device__ __forceinline__ void mbar_wait(uint32_t a, uint32_t parity) {
    asm volatile(
        "{\n\t.reg .pred P;\n\t"
        "WL_%=:\n\t"
        "mbarrier.try_wait.parity.acquire.cta.shared::cta.b64 P, [%0], %1, 0x989680;\n\t"
        "@!P bra WL_%=;\n\t}"
        :: "r"(a), "r"(parity) : "memory");
}
#define LDSM4(r0, r1, r2, r3, addr)                                              \
    asm volatile("ldmatrix.sync.aligned.m8n8.x4.shared.b16 {%0,%1,%2,%3}, [%4];" \
                 : "=r"(r0), "=r"(r1), "=r"(r2), "=r"(r3) : "r"(addr))
#define MMAF16(c, a, b0, b1)                                                  \
    asm volatile("mma.sync.aligned.m16n8k16.row.col.f32.f16.f16.f32 "         \
                 "{%0,%1,%2,%3},{%4,%5,%6,%7},{%8,%9},{%0,%1,%2,%3};"         \
                 : "+f"((c)[0]), "+f"((c)[1]), "+f"((c)[2]), "+f"((c)[3])     \
                 : "r"((a)[0]), "r"((a)[1]), "r"((a)[2]), "r"((a)[3]),        \
                   "r"(b0), "r"(b1))

// 128B-row swizzle (validated since R7): 16B-chunk' = ch ^ (row&7)
__device__ __forceinline__ uint32_t swof(int row, int ch) {
    return (uint32_t)(row * 128 + ((ch ^ (row & 7)) << 4));
}

// ---------------- merged pre-kernel: cvt x + cvt W + gate-combine ----------------
union H8 { __half2 h[4]; uint4 u; };

__device__ __forceinline__ void cvt8h(const float* src, __half* dst, size_t i) {
    float4 v0 = *(const float4*)(src + i);
    float4 v1 = *(const float4*)(src + i + 4);
    H8 o;
    o.h[0] = __float22half2_rn(make_float2(v0.x, v0.y));
    o.h[1] = __float22half2_rn(make_float2(v0.z, v0.w));
    o.h[2] = __float22half2_rn(make_float2(v1.x, v1.y));
    o.h[3] = __float22half2_rn(make_float2(v1.z, v1.w));
    *(uint4*)(dst + i) = o.u;
}
// blocks [0,16384): cvt x; [16384,18432): cvt W_org; [18432,18944): combine
__global__ void k_cvt(const float* __restrict__ x,
                      const float* __restrict__ W_org,
                      const float* __restrict__ gate,
                      const float* __restrict__ W_up) {
    int bb = blockIdx.x;
    if (bb < 16384) {
        size_t i = ((size_t)bb * 256 + threadIdx.x) * 8;
        cvt8h(x, g_x16, i);
    } else if (bb < 18432) {
        size_t i = ((size_t)(bb - 16384) * 256 + threadIdx.x) * 8;
        cvt8h(W_org, g_w16, i);
    } else {
        int idx = (bb - 18432) * 256 + threadIdx.x;
        if (idx >= NB * NDOUT * NR) return;
        int b = idx / (NDOUT * NR);
        int orr = idx - b * (NDOUT * NR);
        int o = orr >> 4, r = orr & 15;
        float s = 0.f;
#pragma unroll
        for (int e = 0; e < NE; e++)
            s += __ldg(&gate[b * NE + e]) * __ldg(&W_up[(size_t)e * NDOUT * NR + orr]);
        size_t off = ((size_t)b * NDOUT + o) * 64;
        g_cb16[off + r] = __float2half_rn(s);
        if (r < 6) {  // zero cols 16..63
            uint4 z = make_uint4(0, 0, 0, 0);
            *(uint4*)&g_cb16[off + 16 + r * 8] = z;
        }
    }
}

// ---------------- k_lx: lx[m,0:16] = x @ W_down^T via fp16 mma ----------------
// 256 blocks x 64 rows, 128 threads (4 warps x 16 rows), 2 blocks/SM, 1 wave
#define LXW 65536                        // 16 n-rows x 2048 k x 2B (fp16 W_down)
#define LX_ROWS 64
#define LX_STG (LX_ROWS * 128)           // 8192: 64 rows x 64 k x 2B (128B rows)
#define LX_SMEM (LXW + 3 * LX_STG)       // 90112 -> 2 blocks/SM
#define LXCK 64
#define LXNCH (NDIN / LXCK)              // 32

__device__ __forceinline__ void lx_issue(uint32_t sb, int s, int c, int rowBase, int tid) {
    uint32_t xs = sb + LXW + s * LX_STG;
#pragma unroll
    for (int j = 0; j < 4; j++) {        // 512 cp16 total / 128 threads
        int g = tid + 128 * j;
        int row = g >> 3, ch = g & 7;
        cp16(xs + swof(row, ch),
             g_x16 + (size_t)(rowBase + row) * NDIN + c * LXCK + ch * 8);
    }
}

__global__ void __launch_bounds__(128, 2) k_lx(const float* __restrict__ Wd) {
    extern __shared__ char sm[];
    const uint32_t sb = smem_u32(sm);
    const int tid = threadIdx.x;
    const int w = tid >> 5, lane = tid & 31;
    const int rowBase = blockIdx.x * LX_ROWS;
    const int lr = lane & 15, lc = lane >> 4;

    // stage W_down fp32 -> fp16 smem [n][2048], 4KB rows, ch^(n&7) swizzle
    for (int idx = tid; idx < 16 * 256; idx += 128) {
        int n = idx >> 8, ch = idx & 255;
        const float* s8 = Wd + (size_t)n * NDIN + ch * 8;
        float4 v0 = *(const float4*)s8;
        float4 v1 = *(const float4*)(s8 + 4);
        H8 o;
        o.h[0] = __float22half2_rn(make_float2(v0.x, v0.y));
        o.h[1] = __float22half2_rn(make_float2(v0.z, v0.w));
        o.h[2] = __float22half2_rn(make_float2(v1.x, v1.y));
        o.h[3] = __float22half2_rn(make_float2(v1.z, v1.w));
        *(uint4*)(sm + n * 4096 + ((ch ^ (n & 7)) << 4)) = o.u;
    }

    float acc[2][4];                     // one m16 tile per warp, 2 n8 tiles
#pragma unroll
    for (int j = 0; j < 2; j++)
#pragma unroll
        for (int q = 0; q < 4; q++) acc[j][q] = 0.f;

    lx_issue(sb, 0, 0, rowBase, tid); cp_commit();
    lx_issue(sb, 1, 1, rowBase, tid); cp_commit();

    for (int c = 0; c < LXNCH; c++) {
        cp_wait1();
        __syncthreads();
        if (c + 2 < LXNCH) lx_issue(sb, (c + 2) % 3, c + 2, rowBase, tid);
        cp_commit();
        const uint32_t xs = sb + LXW + (c % 3) * LX_STG;
#pragma unroll
        for (int ks = 0; ks < 4; ks++) {
            int K = c * 4 + ks;
            uint32_t chB = (uint32_t)(2 * K + lc);
            uint32_t r0, r1, r2, r3;
            LDSM4(r0, r1, r2, r3, sb + lr * 4096 + ((chB ^ (lr & 7)) << 4));
            uint32_t bf0[2] = {r0, r2}, bf1[2] = {r1, r3};
            int row = w * 16 + lr;
            uint32_t ch = (uint32_t)(ks * 2 + lc);
            uint32_t a[4];
            LDSM4(a[0], a[1], a[2], a[3],
                  xs + row * 128 + ((ch ^ (row & 7)) << 4));
            MMAF16(acc[0], a, bf0[0], bf0[1]);
            MMAF16(acc[1], a, bf1[0], bf1[1]);
        }
        __syncthreads();
    }

    // epilogue: store into 64-wide padded array, zero cols 16-63
    {
        int row = rowBase + w * 16 + (lane >> 2);
#pragma unroll
        for (int nt = 0; nt < 2; nt++) {
            int col = nt * 8 + (lane & 3) * 2;
            *(__half2*)&g_lx16[(size_t)row * 64 + col] =
                __float22half2_rn(make_float2(acc[nt][0], acc[nt][1]));
            *(__half2*)&g_lx16[(size_t)(row + 8) * 64 + col] =
                __float22half2_rn(make_float2(acc[nt][2], acc[nt][3]));
        }
    }
    if (tid < LX_ROWS) {
        int m = rowBase + tid;
        uint4 z = make_uint4(0, 0, 0, 0);
#pragma unroll
        for (int zz = 0; zz < 6; zz++)
            *(uint4*)&g_lx16[(size_t)m * 64 + 16 + zz * 8] = z;
    }
}

// ---------------- main GEMM: fp16, mbarrier pipeline, consume-then-produce ----------------
__global__ void __launch_bounds__(256, 2) k_gemm(float* __restrict__ out) {
    extern __shared__ char smem[];
    const uint32_t sb0 = smem_u32(smem);
    const int tid = threadIdx.x;
    const int wid = tid >> 5, lane = tid & 31;
    const int wm = wid >> 2, wn = wid & 3;      // warp tile 64x32
    const int rowBase = blockIdx.y * BM;
    const int colBase = blockIdx.x * BN;
    const int b = blockIdx.y >> 5;              // NS/BM = 32 row-blocks per batch
    const int lr = lane & 15, lc = lane >> 4;
    const uint32_t sw7 = (uint32_t)(lr & 7);

    // mbarriers: full[s] at s*8, empty[s] at 24 + s*8
    const uint32_t mbF = sb0, mbE = sb0 + 24;
    if (tid == 0) {
#pragma unroll
        for (int s = 0; s < NSTAGE; s++) {
            mbar_init(mbF + s * 8, 256);
            mbar_init(mbE + s * 8, 8);
        }
    }
    __syncthreads();

    const uint32_t aBase0 = (uint32_t)((wm * 64 + lr) * 128);
    const uint32_t bBase0 = OF_B + (uint32_t)((wn * 32 + lr) * 128);
    uint32_t cx[4];
#pragma unroll
    for (int ks = 0; ks < 4; ks++)
        cx[ks] = ((uint32_t)(2 * ks + lc) ^ sw7) << 4;

    const int lrow = tid >> 3, lch = tid & 7;
    const uint32_t so0 = OF_TILE + swof(lrow, lch);
    const __half* aG = g_x16 + (size_t)(rowBase + lrow) * NDIN + lch * 8;
    const __half* bG = g_w16 + (size_t)(colBase + lrow) * NDIN + lch * 8;
    const __half* aL = g_lx16 + (size_t)(rowBase + lrow) * 64 + lch * 8;
    const __half* bL = g_cb16 + ((size_t)b * NDOUT + colBase + lrow) * 64 + lch * 8;

    float acc[4][4][4];
#pragma unroll
    for (int i = 0; i < 4; i++)
#pragma unroll
        for (int j = 0; j < 4; j++)
#pragma unroll
            for (int q = 0; q < 4; q++) acc[i][j][q] = 0.f;

#pragma unroll
    for (int p = 0; p < 2; p++) {   // prologue: chunks 0,1
        uint32_t s = sb0 + p * STAGE_SZ;
#pragma unroll
        for (int j = 0; j < 4; j++) {
            cp16(s + so0 + j * 4096, aG + p * CK + (size_t)j * 32 * NDIN);
            cp16(s + OF_B + so0 + j * 4096, bG + p * CK + (size_t)j * 32 * NDIN);
        }
        cp_arrive_noinc(mbF + p * 8);
    }

    int c_s = 0, c_p = 0;          // consumer cursor
    int p_s = 2, p_p = 1;          // producer cursor (flip-phase; R14-validated)
    for (int kc = 0; kc < NCHTOT; kc++) {
        // ---- consume chunk kc ----
        mbar_wait(mbF + c_s * 8, (uint32_t)c_p);
        const uint32_t Sb = sb0 + OF_TILE + c_s * STAGE_SZ;

        uint32_t bfb[2][4][2];     // B frags, double-buffered by ks parity
        uint32_t a[3][4];          // A frags, triple-buffered (prefetch dist 2)
        {
            uint32_t r0, r1, r2, r3;
            LDSM4(r0, r1, r2, r3, Sb + bBase0 + cx[0]);
            bfb[0][0][0] = r0; bfb[0][0][1] = r2;
            bfb[0][1][0] = r1; bfb[0][1][1] = r3;
            LDSM4(r0, r1, r2, r3, Sb + bBase0 + 2048 + cx[0]);
            bfb[0][2][0] = r0; bfb[0][2][1] = r2;
            bfb[0][3][0] = r1; bfb[0][3][1] = r3;
            LDSM4(a[0][0], a[0][1], a[0][2], a[0][3], Sb + aBase0 + cx[0]);
            LDSM4(a[1][0], a[1][1], a[1][2], a[1][3], Sb + aBase0 + 2048 + cx[0]);
        }
#pragma unroll
        for (int ks = 0; ks < 4; ks++) {
            const int cur = ks & 1;
#pragma unroll
            for (int mt = 0; mt < 4; mt++) {
                const int step = ks * 4 + mt;
                if (mt == 0 && ks < 3) {   // B prefetch, first half
                    uint32_t r0, r1, r2, r3;
                    LDSM4(r0, r1, r2, r3, Sb + bBase0 + cx[ks + 1]);
                    bfb[cur ^ 1][0][0] = r0; bfb[cur ^ 1][0][1] = r2;
                    bfb[cur ^ 1][1][0] = r1; bfb[cur ^ 1][1][1] = r3;
                }
                if (mt == 1 && ks < 3) {   // B prefetch, second half
                    uint32_t r0, r1, r2, r3;
                    LDSM4(r0, r1, r2, r3, Sb + bBase0 + 2048 + cx[ks + 1]);
                    bfb[cur ^ 1][2][0] = r0; bfb[cur ^ 1][2][1] = r2;
                    bfb[cur ^ 1][3][0] = r1; bfb[cur ^ 1][3][1] = r3;
                }
                if (step + 2 < 16) {       // A prefetch, distance 2
                    const int ns = step + 2;
                    uint32_t* an = a[ns % 3];
                    LDSM4(an[0], an[1], an[2], an[3],
                          Sb + aBase0 + (ns & 3) * 2048 + cx[ns >> 2]);
                }
                // early empty-arrive: last smem read of this chunk was the
                // A prefetch at step 13 (ks=3,mt=1); release the slot now.
                if (ks == 3 && mt == 2 && lane == 0)
                    mbar_arrive(mbE + c_s * 8);
                const uint32_t* ac = a[step % 3];
#pragma unroll
                for (int nt = 0; nt < 4; nt++)
                    MMAF16(acc[mt][nt], ac, bfb[cur][nt][0], bfb[cur][nt][1]);
            }
        }
        if (++c_s == NSTAGE) { c_s = 0; c_p ^= 1; }

        // ---- produce chunk kc+2 (after consuming: extra slack on empty-wait) ----
        const int nk = kc + 2;
        if (nk < NCHTOT) {
            mbar_wait(mbE + p_s * 8, (uint32_t)p_p);
            uint32_t s = sb0 + p_s * STAGE_SZ;
            if (nk < NCHUNK) {
#pragma unroll
                for (int j = 0; j < 4; j++) {
                    cp16(s + so0 + j * 4096, aG + nk * CK + (size_t)j * 32 * NDIN);
                    cp16(s + OF_B + so0 + j * 4096, bG + nk * CK + (size_t)j * 32 * NDIN);
                }
            } else {  // LoRA chunk: rows of 64 fp16 = 128B
#pragma unroll
                for (int j = 0; j < 4; j++) {
                    cp16(s + so0 + j * 4096, aL + (size_t)j * 32 * 64);
                    cp16(s + OF_B + so0 + j * 4096, bL + (size_t)j * 32 * 64);
                }
            }
            cp_arrive_noinc(mbF + p_s * 8);
            if (++p_s == NSTAGE) { p_s = 0; p_p ^= 1; }
        }
    }

    // ---------------- epilogue ----------------
#pragma unroll
    for (int mt = 0; mt < 4; mt++) {
#pragma unroll
        for (int nt = 0; nt < 4; nt++) {
            int row = rowBase + wm * 64 + mt * 16 + (lane >> 2);
            int col = colBase + wn * 32 + nt * 8 + (lane & 3) * 2;
            *(float2*)&out[(size_t)row * NDOUT + col] =
                make_float2(acc[mt][nt][0], acc[mt][nt][1]);
            *(float2*)&out[(size_t)(row + 8) * NDOUT + col] =
                make_float2(acc[mt][nt][2], acc[mt][nt][3]);
        }
    }
}

// ---------------- launch ----------------
extern "C" void kernel_launch(void* const* d_in, const int* in_sizes, int n_in,
                              void* d_out, int out_size) {
    const float* x      = (const float*)d_in[0];
    const float* gate   = (const float*)d_in[1];
    const float* W_org  = (const float*)d_in[2];
    const float* W_down = (const float*)d_in[3];
    const float* W_up   = (const float*)d_in[4];
    float* out = (float*)d_out;

    cudaFuncSetAttribute(k_gemm, cudaFuncAttributeMaxDynamicSharedMemorySize, SMEM_TOTAL);
    cudaFuncSetAttribute(k_lx, cudaFuncAttributeMaxDynamicSharedMemorySize, LX_SMEM);

    k_cvt<<<16384 + 2048 + 512, 256>>>(x, W_org, gate, W_up);
    k_lx<<<NM / LX_ROWS, 128, LX_SMEM>>>(W_down);

    dim3 grid(NDOUT / BN, NM / BM);   // (16, 128) = 2048 CTAs
    k_gemm<<<grid, 256, SMEM_TOTAL>>>(out);
}